// round 4
// baseline (speedup 1.0000x reference)
#include <cuda_runtime.h>

#define B_ 8
#define S_ 1024
#define E_ 768
#define H_ 12
#define D_ 64
#define M_ (B_*S_)   // 8192

// Scratch (allocations are forbidden; use device globals)
__device__ float g_q[B_*H_*S_*D_];
__device__ float g_k[B_*H_*S_*D_];
__device__ float g_v[B_*H_*S_*D_];
__device__ float g_x[B_*S_*E_];   // attention output, already head-concatenated [B,S,E]

// ---------------------------------------------------------------------------
// Kernel 1: fused QKV projection.
// C[m, (h,d)] = sum_e hid[m,e] * W[h,e,d] + bias[h,d]
// grid = (M/64, 3*H). blockIdx.y selects (proj, head). 64x64 tile, K-tile 16,
// 256 threads, 4x4 microtile. Output scattered to [B,H,S,D] for attention.
// ---------------------------------------------------------------------------
__global__ __launch_bounds__(256)
void qkv_kernel(const float* __restrict__ hid,
                const float* __restrict__ Wq, const float* __restrict__ Wk,
                const float* __restrict__ Wv,
                const float* __restrict__ bq, const float* __restrict__ bk,
                const float* __restrict__ bv)
{
    __shared__ float AsT[16][64];   // [k][m]
    __shared__ float Bs [16][64];   // [k][n]

    const int tid = threadIdx.x;
    const int tx = tid & 15, ty = tid >> 4;
    const int m0 = blockIdx.x * 64;
    const int nb = blockIdx.y;
    const int proj = nb / H_;            // 0:q 1:k 2:v
    const int h = nb - proj * H_;

    const float* W    = (proj == 0) ? Wq : (proj == 1) ? Wk : Wv;
    const float* bias = (proj == 0) ? bq : (proj == 1) ? bk : bv;
    float* out        = (proj == 0) ? g_q : (proj == 1) ? g_k : g_v;
    const float* Wh = W + (size_t)h * E_ * D_;

    float acc[4][4] = {};

    const int a_row = tid >> 2;          // 0..63
    const int a_k   = (tid & 3) * 4;     // 0,4,8,12
    const int b_k   = tid >> 4;          // 0..15
    const int b_d   = (tid & 15) * 4;    // 0..60

    for (int k0 = 0; k0 < E_; k0 += 16) {
        float4 av = *(const float4*)&hid[(size_t)(m0 + a_row) * E_ + k0 + a_k];
        AsT[a_k + 0][a_row] = av.x;
        AsT[a_k + 1][a_row] = av.y;
        AsT[a_k + 2][a_row] = av.z;
        AsT[a_k + 3][a_row] = av.w;
        *(float4*)&Bs[b_k][b_d] =
            *(const float4*)&Wh[(size_t)(k0 + b_k) * D_ + b_d];
        __syncthreads();
#pragma unroll
        for (int kk = 0; kk < 16; kk++) {
            float4 a4 = *(const float4*)&AsT[kk][ty * 4];
            float4 b4 = *(const float4*)&Bs[kk][tx * 4];
            float a[4] = {a4.x, a4.y, a4.z, a4.w};
            float b[4] = {b4.x, b4.y, b4.z, b4.w};
#pragma unroll
            for (int i = 0; i < 4; i++)
#pragma unroll
                for (int j = 0; j < 4; j++)
                    acc[i][j] += a[i] * b[j];
        }
        __syncthreads();
    }

    float4 bb = *(const float4*)&bias[h * D_ + tx * 4];
#pragma unroll
    for (int i = 0; i < 4; i++) {
        int m = m0 + ty * 4 + i;
        int b = m >> 10;         // / S_
        int s = m & (S_ - 1);
        float* orow = out + (((size_t)(b * H_ + h)) * S_ + s) * D_;
        float4 ov = make_float4(acc[i][0] + bb.x, acc[i][1] + bb.y,
                                acc[i][2] + bb.z, acc[i][3] + bb.w);
        *(float4*)&orow[tx * 4] = ov;
    }
}

// ---------------------------------------------------------------------------
// Kernel 2: flash attention (fp32, non-causal).
// grid = (S/64, B*H), 256 threads. Each block: 64 Q rows, loop over 16 KV
// tiles of 64 rows. Smem operands are k-major for conflict-free LDS.128.
// Output written head-concatenated into g_x [B,S,E].
// ---------------------------------------------------------------------------
__global__ __launch_bounds__(256)
void attn_kernel()
{
    extern __shared__ float sm[];
    float* QsT = sm;               // [d][qrow]   64*64
    float* KsT = sm + 4096;        // [d][kvrow]  64*64
    float* Vs  = sm + 8192;        // [kvrow][d]  64*64
    float* Ps  = sm + 12288;       // [kvrow][qrow] 64*65 (pad for stores)

    const int tid = threadIdx.x;
    const int tx = tid & 15, ty = tid >> 4;
    const int bh = blockIdx.y;          // b*H + h
    const int s0 = blockIdx.x * 64;
    const int b = bh / H_;
    const int h = bh - b * H_;

    const float* Q = g_q + (size_t)bh * S_ * D_;
    const float* K = g_k + (size_t)bh * S_ * D_;
    const float* V = g_v + (size_t)bh * S_ * D_;

    // load Q tile, transposed to [d][qrow]
#pragma unroll
    for (int p = 0; p < 4; p++) {
        int fid = p * 256 + tid;
        int row = fid >> 4;
        int dq  = (fid & 15) * 4;
        float4 qv = *(const float4*)&Q[(size_t)(s0 + row) * D_ + dq];
        QsT[(dq + 0) * 64 + row] = qv.x;
        QsT[(dq + 1) * 64 + row] = qv.y;
        QsT[(dq + 2) * 64 + row] = qv.z;
        QsT[(dq + 3) * 64 + row] = qv.w;
    }

    float m_i[4], l_i[4], o[4][4];
#pragma unroll
    for (int i = 0; i < 4; i++) {
        m_i[i] = -1e30f; l_i[i] = 0.f;
#pragma unroll
        for (int j = 0; j < 4; j++) o[i][j] = 0.f;
    }

    for (int t0 = 0; t0 < S_; t0 += 64) {
        // load K (transposed) and V tiles
#pragma unroll
        for (int p = 0; p < 4; p++) {
            int fid = p * 256 + tid;
            int row = fid >> 4;
            int dq  = (fid & 15) * 4;
            float4 kv4 = *(const float4*)&K[(size_t)(t0 + row) * D_ + dq];
            KsT[(dq + 0) * 64 + row] = kv4.x;
            KsT[(dq + 1) * 64 + row] = kv4.y;
            KsT[(dq + 2) * 64 + row] = kv4.z;
            KsT[(dq + 3) * 64 + row] = kv4.w;
            *(float4*)&Vs[row * 64 + dq] =
                *(const float4*)&V[(size_t)(t0 + row) * D_ + dq];
        }
        __syncthreads();

        // S = Q K^T (per-thread 4x4)
        float sc[4][4] = {};
#pragma unroll
        for (int kd = 0; kd < 64; kd++) {
            float4 a4 = *(const float4*)&QsT[kd * 64 + ty * 4];
            float4 b4 = *(const float4*)&KsT[kd * 64 + tx * 4];
            float a[4] = {a4.x, a4.y, a4.z, a4.w};
            float bb[4] = {b4.x, b4.y, b4.z, b4.w};
#pragma unroll
            for (int i = 0; i < 4; i++)
#pragma unroll
                for (int j = 0; j < 4; j++)
                    sc[i][j] += a[i] * bb[j];
        }

        // online softmax (rows owned by (ty,i), 16 tx lanes share a row)
#pragma unroll
        for (int i = 0; i < 4; i++) {
            float mx = -1e30f;
#pragma unroll
            for (int j = 0; j < 4; j++) {
                sc[i][j] *= 0.125f;          // 1/sqrt(64)
                mx = fmaxf(mx, sc[i][j]);
            }
#pragma unroll
            for (int off = 8; off > 0; off >>= 1)
                mx = fmaxf(mx, __shfl_xor_sync(0xffffffffu, mx, off));
            float mnew = fmaxf(m_i[i], mx);
            float corr = __expf(m_i[i] - mnew);
            float rs = 0.f;
#pragma unroll
            for (int j = 0; j < 4; j++) {
                float p = __expf(sc[i][j] - mnew);
                Ps[(tx * 4 + j) * 65 + ty * 4 + i] = p;
                rs += p;
            }
#pragma unroll
            for (int off = 8; off > 0; off >>= 1)
                rs += __shfl_xor_sync(0xffffffffu, rs, off);
            l_i[i] = l_i[i] * corr + rs;
            m_i[i] = mnew;
#pragma unroll
            for (int j = 0; j < 4; j++) o[i][j] *= corr;
        }
        __syncthreads();

        // O += P @ V
#pragma unroll
        for (int kd = 0; kd < 64; kd++) {
            float pr[4];
#pragma unroll
            for (int i = 0; i < 4; i++)
                pr[i] = Ps[kd * 65 + ty * 4 + i];
            float4 v4 = *(const float4*)&Vs[kd * 64 + tx * 4];
            float vv[4] = {v4.x, v4.y, v4.z, v4.w};
#pragma unroll
            for (int i = 0; i < 4; i++)
#pragma unroll
                for (int j = 0; j < 4; j++)
                    o[i][j] += pr[i] * vv[j];
        }
        __syncthreads();
    }

    // finalize + write head-concatenated
#pragma unroll
    for (int i = 0; i < 4; i++) {
        float inv = 1.f / l_i[i];
        int qr = s0 + ty * 4 + i;
        float* row = g_x + ((size_t)b * S_ + qr) * E_ + h * D_;
        float4 ov = make_float4(o[i][0] * inv, o[i][1] * inv,
                                o[i][2] * inv, o[i][3] * inv);
        *(float4*)&row[tx * 4] = ov;
    }
}

// ---------------------------------------------------------------------------
// Kernel 3: output projection.  out = g_x @ Wo + bo.  grid = (M/64, E/64).
// ---------------------------------------------------------------------------
__global__ __launch_bounds__(256)
void proj_kernel(const float* __restrict__ Wo, const float* __restrict__ bo,
                 float* __restrict__ out)
{
    __shared__ float AsT[16][64];
    __shared__ float Bs [16][64];

    const int tid = threadIdx.x;
    const int tx = tid & 15, ty = tid >> 4;
    const int m0 = blockIdx.x * 64;
    const int n0 = blockIdx.y * 64;

    float acc[4][4] = {};

    const int a_row = tid >> 2;
    const int a_k   = (tid & 3) * 4;
    const int b_k   = tid >> 4;
    const int b_d   = (tid & 15) * 4;

    for (int k0 = 0; k0 < E_; k0 += 16) {
        float4 av = *(const float4*)&g_x[(size_t)(m0 + a_row) * E_ + k0 + a_k];
        AsT[a_k + 0][a_row] = av.x;
        AsT[a_k + 1][a_row] = av.y;
        AsT[a_k + 2][a_row] = av.z;
        AsT[a_k + 3][a_row] = av.w;
        *(float4*)&Bs[b_k][b_d] =
            *(const float4*)&Wo[(size_t)(k0 + b_k) * E_ + n0 + b_d];
        __syncthreads();
#pragma unroll
        for (int kk = 0; kk < 16; kk++) {
            float4 a4 = *(const float4*)&AsT[kk][ty * 4];
            float4 b4 = *(const float4*)&Bs[kk][tx * 4];
            float a[4] = {a4.x, a4.y, a4.z, a4.w};
            float b[4] = {b4.x, b4.y, b4.z, b4.w};
#pragma unroll
            for (int i = 0; i < 4; i++)
#pragma unroll
                for (int j = 0; j < 4; j++)
                    acc[i][j] += a[i] * b[j];
        }
        __syncthreads();
    }

    float4 bb = *(const float4*)&bo[n0 + tx * 4];
#pragma unroll
    for (int i = 0; i < 4; i++) {
        int m = m0 + ty * 4 + i;
        float4 ov = make_float4(acc[i][0] + bb.x, acc[i][1] + bb.y,
                                acc[i][2] + bb.z, acc[i][3] + bb.w);
        *(float4*)&out[(size_t)m * E_ + n0 + tx * 4] = ov;
    }
}

// ---------------------------------------------------------------------------

extern "C" void kernel_launch(void* const* d_in, const int* in_sizes, int n_in,
                              void* d_out, int out_size)
{
    const float* hid = (const float*)d_in[0];
    const float* Wq  = (const float*)d_in[1];
    const float* Wk  = (const float*)d_in[2];
    const float* Wv  = (const float*)d_in[3];
    const float* bq  = (const float*)d_in[4];
    const float* bk  = (const float*)d_in[5];
    const float* bv  = (const float*)d_in[6];
    const float* Wo  = (const float*)d_in[7];
    const float* bo  = (const float*)d_in[8];
    float* out = (float*)d_out;

    const int attn_smem = (3 * 64 * 64 + 64 * 65) * (int)sizeof(float); // 65792
    cudaFuncSetAttribute(attn_kernel,
                         cudaFuncAttributeMaxDynamicSharedMemorySize, attn_smem);

    qkv_kernel<<<dim3(M_ / 64, 3 * H_), 256>>>(hid, Wq, Wk, Wv, bq, bk, bv);
    attn_kernel<<<dim3(S_ / 64, B_ * H_), 256, attn_smem>>>();
    proj_kernel<<<dim3(M_ / 64, E_ / 64), 256>>>(Wo, bo, out);
}

// round 12
// speedup vs baseline: 1.0568x; 1.0568x over previous
#include <cuda_runtime.h>

#define B_ 8
#define S_ 1024
#define E_ 768
#define H_ 12
#define D_ 64
#define M_ (B_*S_)   // 8192

// Scratch (allocations are forbidden; use device globals)
__device__ float g_q[B_*H_*S_*D_];
__device__ float g_k[B_*H_*S_*D_];
__device__ float g_v[B_*H_*S_*D_];
__device__ float g_x[B_*S_*E_];   // attention output, already head-concatenated [B,S,E]

// ---------------------------------------------------------------------------
// Kernel 1: fused QKV projection.
// C[m, (h,d)] = sum_e hid[m,e] * W[h,e,d] + bias[h,d]
// grid = (M/64, 3*H). blockIdx.y selects (proj, head). 64x64 tile, K-tile 16,
// 256 threads, 4x4 microtile. Output scattered to [B,H,S,D] for attention.
// ---------------------------------------------------------------------------
__global__ __launch_bounds__(256)
void qkv_kernel_r12(const float* __restrict__ hid,
                    const float* __restrict__ Wq, const float* __restrict__ Wk,
                    const float* __restrict__ Wv,
                    const float* __restrict__ bq, const float* __restrict__ bk,
                    const float* __restrict__ bv)
{
    __shared__ float AsT[16][64];   // [k][m]
    __shared__ float Bs [16][64];   // [k][n]

    const int tid = threadIdx.x;
    const int tx = tid & 15, ty = tid >> 4;
    const int m0 = blockIdx.x * 64;
    const int nb = blockIdx.y;
    const int proj = nb / H_;            // 0:q 1:k 2:v
    const int h = nb - proj * H_;

    const float* W    = (proj == 0) ? Wq : (proj == 1) ? Wk : Wv;
    const float* bias = (proj == 0) ? bq : (proj == 1) ? bk : bv;
    float* out        = (proj == 0) ? g_q : (proj == 1) ? g_k : g_v;
    const float* Wh = W + (size_t)h * E_ * D_;

    float acc[4][4] = {};

    const int a_row = tid >> 2;          // 0..63
    const int a_k   = (tid & 3) * 4;     // 0,4,8,12
    const int b_k   = tid >> 4;          // 0..15
    const int b_d   = (tid & 15) * 4;    // 0..60

    for (int k0 = 0; k0 < E_; k0 += 16) {
        float4 av = *(const float4*)&hid[(size_t)(m0 + a_row) * E_ + k0 + a_k];
        AsT[a_k + 0][a_row] = av.x;
        AsT[a_k + 1][a_row] = av.y;
        AsT[a_k + 2][a_row] = av.z;
        AsT[a_k + 3][a_row] = av.w;
        *(float4*)&Bs[b_k][b_d] =
            *(const float4*)&Wh[(size_t)(k0 + b_k) * D_ + b_d];
        __syncthreads();
#pragma unroll
        for (int kk = 0; kk < 16; kk++) {
            float4 a4 = *(const float4*)&AsT[kk][ty * 4];
            float4 b4 = *(const float4*)&Bs[kk][tx * 4];
            float a[4] = {a4.x, a4.y, a4.z, a4.w};
            float b[4] = {b4.x, b4.y, b4.z, b4.w};
#pragma unroll
            for (int i = 0; i < 4; i++)
#pragma unroll
                for (int j = 0; j < 4; j++)
                    acc[i][j] += a[i] * b[j];
        }
        __syncthreads();
    }

    float4 bb = *(const float4*)&bias[h * D_ + tx * 4];
#pragma unroll
    for (int i = 0; i < 4; i++) {
        int m = m0 + ty * 4 + i;
        int b = m >> 10;         // / S_
        int s = m & (S_ - 1);
        float* orow = out + (((size_t)(b * H_ + h)) * S_ + s) * D_;
        float4 ov = make_float4(acc[i][0] + bb.x, acc[i][1] + bb.y,
                                acc[i][2] + bb.z, acc[i][3] + bb.w);
        *(float4*)&orow[tx * 4] = ov;
    }
}

// ---------------------------------------------------------------------------
// Kernel 2: flash attention (fp32, non-causal).
// grid = (S/64, B*H), 256 threads. Each block: 64 Q rows, loop over 16 KV
// tiles of 64 rows. Smem operands are k-major for conflict-free LDS.128.
// Output written head-concatenated into g_x [B,S,E].
// ---------------------------------------------------------------------------
__global__ __launch_bounds__(256)
void attn_kernel_r12()
{
    extern __shared__ float sm[];
    float* QsT = sm;               // [d][qrow]   64*64
    float* KsT = sm + 4096;        // [d][kvrow]  64*64
    float* Vs  = sm + 8192;        // [kvrow][d]  64*64
    float* Ps  = sm + 12288;       // [kvrow][qrow] 64*65 (pad for stores)

    const int tid = threadIdx.x;
    const int tx = tid & 15, ty = tid >> 4;
    const int bh = blockIdx.y;          // b*H + h
    const int s0 = blockIdx.x * 64;
    const int b = bh / H_;
    const int h = bh - b * H_;

    const float* Q = g_q + (size_t)bh * S_ * D_;
    const float* K = g_k + (size_t)bh * S_ * D_;
    const float* V = g_v + (size_t)bh * S_ * D_;

    // load Q tile, transposed to [d][qrow]
#pragma unroll
    for (int p = 0; p < 4; p++) {
        int fid = p * 256 + tid;
        int row = fid >> 4;
        int dq  = (fid & 15) * 4;
        float4 qv = *(const float4*)&Q[(size_t)(s0 + row) * D_ + dq];
        QsT[(dq + 0) * 64 + row] = qv.x;
        QsT[(dq + 1) * 64 + row] = qv.y;
        QsT[(dq + 2) * 64 + row] = qv.z;
        QsT[(dq + 3) * 64 + row] = qv.w;
    }

    float m_i[4], l_i[4], o[4][4];
#pragma unroll
    for (int i = 0; i < 4; i++) {
        m_i[i] = -1e30f; l_i[i] = 0.f;
#pragma unroll
        for (int j = 0; j < 4; j++) o[i][j] = 0.f;
    }

    for (int t0 = 0; t0 < S_; t0 += 64) {
        // load K (transposed) and V tiles
#pragma unroll
        for (int p = 0; p < 4; p++) {
            int fid = p * 256 + tid;
            int row = fid >> 4;
            int dq  = (fid & 15) * 4;
            float4 kv4 = *(const float4*)&K[(size_t)(t0 + row) * D_ + dq];
            KsT[(dq + 0) * 64 + row] = kv4.x;
            KsT[(dq + 1) * 64 + row] = kv4.y;
            KsT[(dq + 2) * 64 + row] = kv4.z;
            KsT[(dq + 3) * 64 + row] = kv4.w;
            *(float4*)&Vs[row * 64 + dq] =
                *(const float4*)&V[(size_t)(t0 + row) * D_ + dq];
        }
        __syncthreads();

        // S = Q K^T (per-thread 4x4)
        float sc[4][4] = {};
#pragma unroll
        for (int kd = 0; kd < 64; kd++) {
            float4 a4 = *(const float4*)&QsT[kd * 64 + ty * 4];
            float4 b4 = *(const float4*)&KsT[kd * 64 + tx * 4];
            float a[4] = {a4.x, a4.y, a4.z, a4.w};
            float bb[4] = {b4.x, b4.y, b4.z, b4.w};
#pragma unroll
            for (int i = 0; i < 4; i++)
#pragma unroll
                for (int j = 0; j < 4; j++)
                    sc[i][j] += a[i] * bb[j];
        }

        // online softmax (rows owned by (ty,i), 16 tx lanes share a row)
#pragma unroll
        for (int i = 0; i < 4; i++) {
            float mx = -1e30f;
#pragma unroll
            for (int j = 0; j < 4; j++) {
                sc[i][j] *= 0.125f;          // 1/sqrt(64)
                mx = fmaxf(mx, sc[i][j]);
            }
#pragma unroll
            for (int off = 8; off > 0; off >>= 1)
                mx = fmaxf(mx, __shfl_xor_sync(0xffffffffu, mx, off));
            float mnew = fmaxf(m_i[i], mx);
            float corr = __expf(m_i[i] - mnew);
            float rs = 0.f;
#pragma unroll
            for (int j = 0; j < 4; j++) {
                float p = __expf(sc[i][j] - mnew);
                Ps[(tx * 4 + j) * 65 + ty * 4 + i] = p;
                rs += p;
            }
#pragma unroll
            for (int off = 8; off > 0; off >>= 1)
                rs += __shfl_xor_sync(0xffffffffu, rs, off);
            l_i[i] = l_i[i] * corr + rs;
            m_i[i] = mnew;
#pragma unroll
            for (int j = 0; j < 4; j++) o[i][j] *= corr;
        }
        __syncthreads();

        // O += P @ V
#pragma unroll
        for (int kd = 0; kd < 64; kd++) {
            float pr[4];
#pragma unroll
            for (int i = 0; i < 4; i++)
                pr[i] = Ps[kd * 65 + ty * 4 + i];
            float4 v4 = *(const float4*)&Vs[kd * 64 + tx * 4];
            float vv[4] = {v4.x, v4.y, v4.z, v4.w};
#pragma unroll
            for (int i = 0; i < 4; i++)
#pragma unroll
                for (int j = 0; j < 4; j++)
                    o[i][j] += pr[i] * vv[j];
        }
        __syncthreads();
    }

    // finalize + write head-concatenated
#pragma unroll
    for (int i = 0; i < 4; i++) {
        float inv = 1.f / l_i[i];
        int qr = s0 + ty * 4 + i;
        float* row = g_x + ((size_t)b * S_ + qr) * E_ + h * D_;
        float4 ov = make_float4(o[i][0] * inv, o[i][1] * inv,
                                o[i][2] * inv, o[i][3] * inv);
        *(float4*)&row[tx * 4] = ov;
    }
}

// ---------------------------------------------------------------------------
// Kernel 3: output projection.  out = g_x @ Wo + bo.  grid = (M/64, E/64).
// ---------------------------------------------------------------------------
__global__ __launch_bounds__(256)
void proj_kernel_r12(const float* __restrict__ Wo, const float* __restrict__ bo,
                     float* __restrict__ out)
{
    __shared__ float AsT[16][64];
    __shared__ float Bs [16][64];

    const int tid = threadIdx.x;
    const int tx = tid & 15, ty = tid >> 4;
    const int m0 = blockIdx.x * 64;
    const int n0 = blockIdx.y * 64;

    float acc[4][4] = {};

    const int a_row = tid >> 2;
    const int a_k   = (tid & 3) * 4;
    const int b_k   = tid >> 4;
    const int b_d   = (tid & 15) * 4;

    for (int k0 = 0; k0 < E_; k0 += 16) {
        float4 av = *(const float4*)&g_x[(size_t)(m0 + a_row) * E_ + k0 + a_k];
        AsT[a_k + 0][a_row] = av.x;
        AsT[a_k + 1][a_row] = av.y;
        AsT[a_k + 2][a_row] = av.z;
        AsT[a_k + 3][a_row] = av.w;
        *(float4*)&Bs[b_k][b_d] =
            *(const float4*)&Wo[(size_t)(k0 + b_k) * E_ + n0 + b_d];
        __syncthreads();
#pragma unroll
        for (int kk = 0; kk < 16; kk++) {
            float4 a4 = *(const float4*)&AsT[kk][ty * 4];
            float4 b4 = *(const float4*)&Bs[kk][tx * 4];
            float a[4] = {a4.x, a4.y, a4.z, a4.w};
            float b[4] = {b4.x, b4.y, b4.z, b4.w};
#pragma unroll
            for (int i = 0; i < 4; i++)
#pragma unroll
                for (int j = 0; j < 4; j++)
                    acc[i][j] += a[i] * b[j];
        }
        __syncthreads();
    }

    float4 bb = *(const float4*)&bo[n0 + tx * 4];
#pragma unroll
    for (int i = 0; i < 4; i++) {
        int m = m0 + ty * 4 + i;
        float4 ov = make_float4(acc[i][0] + bb.x, acc[i][1] + bb.y,
                                acc[i][2] + bb.z, acc[i][3] + bb.w);
        *(float4*)&out[(size_t)m * E_ + n0 + tx * 4] = ov;
    }
}

// ---------------------------------------------------------------------------

extern "C" void kernel_launch(void* const* d_in, const int* in_sizes, int n_in,
                              void* d_out, int out_size)
{
    const float* hid = (const float*)d_in[0];
    const float* Wq  = (const float*)d_in[1];
    const float* Wk  = (const float*)d_in[2];
    const float* Wv  = (const float*)d_in[3];
    const float* bq  = (const float*)d_in[4];
    const float* bk  = (const float*)d_in[5];
    const float* bv  = (const float*)d_in[6];
    const float* Wo  = (const float*)d_in[7];
    const float* bo  = (const float*)d_in[8];
    float* out = (float*)d_out;

    const int attn_smem = (3 * 64 * 64 + 64 * 65) * (int)sizeof(float); // 65792
    cudaFuncSetAttribute(attn_kernel_r12,
                         cudaFuncAttributeMaxDynamicSharedMemorySize, attn_smem);

    qkv_kernel_r12<<<dim3(M_ / 64, 3 * H_), 256>>>(hid, Wq, Wk, Wv, bq, bk, bv);
    attn_kernel_r12<<<dim3(S_ / 64, B_ * H_), 256, attn_smem>>>();
    proj_kernel_r12<<<dim3(M_ / 64, E_ / 64), 256>>>(Wo, bo, out);
}

// round 13
// speedup vs baseline: 1.4909x; 1.4107x over previous
#include <cuda_runtime.h>
#include <cuda_fp16.h>
#include <cstdint>

#define B_ 8
#define S_ 1024
#define E_ 768
#define H_ 12
#define D_ 64
#define M_ (B_*S_)   // 8192

// ---------------------------------------------------------------------------
// Scratch (allocations are forbidden; use device globals)
// NOTE: device globals must ONLY be referenced inside device code. Passing
// them as kernel arguments from host code silently reads the host-side
// shadow symbol via HMM/ATS on GB300 (root cause of rounds 6-11 failing).
// ---------------------------------------------------------------------------
__device__ float g_q[B_*H_*S_*D_];
__device__ float g_k[B_*H_*S_*D_];
__device__ float g_v[B_*H_*S_*D_];
__device__ float g_x[B_*S_*E_];   // attention output, head-concatenated [B,S,E]

// ---------------------------------------------------------------------------
// fp16 m16n8k16 MMA (PTX ISA layouts, g = lane>>2, c = lane&3):
//   A regs (row-major 16x16): a0=(g, 2c:2c+1)  a1=(g+8, 2c:2c+1)
//                             a2=(g, 2c+8:2c+9) a3=(g+8, 2c+8:2c+9)
//   B regs (col-major 16x8):  b0=(k=2c:2c+1, n=g)  b1=(k=2c+8:2c+9, n=g)
//   C regs (16x8 fp32): c0,c1=(g,2c),(g,2c+1); c2,c3=(g+8,2c),(g+8,2c+1)
// ---------------------------------------------------------------------------
__device__ __forceinline__ void mma_f16(float c[4], const uint32_t a[4],
                                        const uint32_t b[2]) {
    asm volatile(
        "mma.sync.aligned.m16n8k16.row.col.f32.f16.f16.f32 "
        "{%0,%1,%2,%3}, {%4,%5,%6,%7}, {%8,%9}, {%0,%1,%2,%3};"
        : "+f"(c[0]), "+f"(c[1]), "+f"(c[2]), "+f"(c[3])
        : "r"(a[0]), "r"(a[1]), "r"(a[2]), "r"(a[3]), "r"(b[0]), "r"(b[1]));
}

__device__ __forceinline__ void split_f16(float x, __half& hi, __half& lo) {
    hi = __float2half_rn(x);
    lo = __float2half_rn(x - __half2float(hi));
}

// ---------------------------------------------------------------------------
// fp32-accurate GEMM via fp16 hi/lo split HMMA.
// D = Ahi*Bhi + Ahi*Blo + Alo*Bhi   (error ~2^-22)
// Block tile 128(M) x 128(N), K-chunk 32, 256 threads = 8 warps (2x4),
// warp tile 64x32. LDG->reg->STS staging with register prefetch,
// single smem buffer (static, 37888 B).
//   Ahi/Alo: [128 rows][40 halfs]  (20-word stride; frag banks CF)
//   Bhi/Blo: [16 k2-rows][136 half2] (136-word stride; frag banks 8c+g: CF)
// QKV=true : A = hid (arg), B(k,n) = W_proj[h][e=k][d], N total = 2304
// QKV=false: A = g_x (device global, bound IN KERNEL), B = Wo, N = 768
// ---------------------------------------------------------------------------
#define NKT 24   // 768/32

template <bool QKV>
__global__ __launch_bounds__(256, 1)
void gemm_hl_r13(const float* __restrict__ AsrcArg,
                 const float* __restrict__ Wq, const float* __restrict__ Wk,
                 const float* __restrict__ Wv,
                 const float* __restrict__ bq, const float* __restrict__ bk,
                 const float* __restrict__ bv,
                 const float* __restrict__ Wo, const float* __restrict__ bo,
                 float* __restrict__ dout)
{
    __shared__ __align__(16) __half Ahi[128 * 40];
    __shared__ __align__(16) __half Alo[128 * 40];
    __shared__ __align__(16) __half Bhi[16 * 272];   // 16 k2-rows x 136 half2
    __shared__ __align__(16) __half Blo[16 * 272];

    // A source: device global bound inside device code for the proj GEMM.
    const float* Asrc = QKV ? AsrcArg : (const float*)g_x;

    const int tid  = threadIdx.x;
    const int wid  = tid >> 5, lane = tid & 31;
    const int g    = lane >> 2, c = lane & 3;
    const int wm   = wid >> 2;          // 0..1
    const int wn   = wid & 3;           // 0..3

    const int m0 = blockIdx.x * 128;
    const int n0 = blockIdx.y * 128;

    // ---- staging descriptors: 4 float4 each for A and B per chunk ----
    const float* aptr[4];
    int arow[4], ac4[4];
#pragma unroll
    for (int i = 0; i < 4; i++) {
        int f = tid + i * 256;          // 0..1023
        arow[i] = f >> 3;               // 0..127
        ac4[i]  = f & 7;                // 0..7 (float4 along 32-wide k)
        aptr[i] = Asrc + (size_t)(m0 + arow[i]) * E_ + ac4[i] * 4;
    }
    const float* bptr[4];
    int bkr[4], bn[4];
#pragma unroll
    for (int i = 0; i < 4; i++) {
        int f = tid + i * 256;
        bkr[i] = f >> 5;                // 0..31 (k within chunk)
        bn[i]  = (f & 31) * 4;          // 0..124 (n start)
        int n  = n0 + bn[i];
        if (QKV) {
            int proj = n / 768;
            int rem  = n - proj * 768;
            int h = rem >> 6, d = rem & 63;
            const float* W = (proj == 0) ? Wq : (proj == 1) ? Wk : Wv;
            bptr[i] = W + (size_t)h * E_ * D_ + (size_t)bkr[i] * D_ + d;
        } else {
            bptr[i] = Wo + (size_t)bkr[i] * E_ + n;
        }
    }
    const int badv = QKV ? 32 * D_ : 32 * E_;

    float Cacc[4][4][4];
#pragma unroll
    for (int ms = 0; ms < 4; ms++)
#pragma unroll
        for (int ns = 0; ns < 4; ns++)
#pragma unroll
            for (int r = 0; r < 4; r++) Cacc[ms][ns][r] = 0.f;

    float4 aReg[4], bReg[4];

    // store helpers -----------------------------------------------------
    auto store_a = [&](int i, const float4& v) {
        __half h0, l0, h1, l1, h2, l2, h3, l3;
        split_f16(v.x, h0, l0); split_f16(v.y, h1, l1);
        split_f16(v.z, h2, l2); split_f16(v.w, h3, l3);
        __half* ah = &Ahi[arow[i] * 40 + ac4[i] * 4];
        __half* al = &Alo[arow[i] * 40 + ac4[i] * 4];
        *(__half2*)&ah[0] = __halves2half2(h0, h1);
        *(__half2*)&ah[2] = __halves2half2(h2, h3);
        *(__half2*)&al[0] = __halves2half2(l0, l1);
        *(__half2*)&al[2] = __halves2half2(l2, l3);
    };
    auto store_b = [&](int i, const float4& v) {
        // B stored k-paired: half2 element (k even, k odd) at [k>>1][n]
        const int base = (bkr[i] >> 1) * 272 + bn[i] * 2 + (bkr[i] & 1);
        float xs[4] = {v.x, v.y, v.z, v.w};
#pragma unroll
        for (int j = 0; j < 4; j++) {
            __half h, l;
            split_f16(xs[j], h, l);
            Bhi[base + j * 2] = h;
            Blo[base + j * 2] = l;
        }
    };

    // ---- prologue: load chunk 0, convert, store to smem ----
#pragma unroll
    for (int i = 0; i < 4; i++) aReg[i] = *(const float4*)aptr[i];
#pragma unroll
    for (int i = 0; i < 4; i++) bReg[i] = *(const float4*)bptr[i];
#pragma unroll
    for (int i = 0; i < 4; i++) store_a(i, aReg[i]);
#pragma unroll
    for (int i = 0; i < 4; i++) store_b(i, bReg[i]);
    __syncthreads();

    const uint32_t* Ahi32 = (const uint32_t*)Ahi;
    const uint32_t* Alo32 = (const uint32_t*)Alo;
    const uint32_t* Bhi32 = (const uint32_t*)Bhi;
    const uint32_t* Blo32 = (const uint32_t*)Blo;

    for (int t = 0; t < NKT; t++) {
        // prefetch next chunk into registers (overlaps with compute)
        if (t + 1 < NKT) {
#pragma unroll
            for (int i = 0; i < 4; i++) {
                aptr[i] += 32;
                aReg[i] = *(const float4*)aptr[i];
            }
#pragma unroll
            for (int i = 0; i < 4; i++) {
                bptr[i] += badv;
                bReg[i] = *(const float4*)bptr[i];
            }
        }

        // ---- compute chunk t: two k16 steps ----
#pragma unroll
        for (int s = 0; s < 2; s++) {
            uint32_t ahi[4][4], alo[4][4];
#pragma unroll
            for (int ms = 0; ms < 4; ms++) {
                const int aw = (wm * 64 + ms * 16 + g) * 20 + s * 8 + c;
                ahi[ms][0] = Ahi32[aw];        // (g,   k=2c:2c+1)
                ahi[ms][1] = Ahi32[aw + 160];  // (g+8) +8 rows * 20 words
                ahi[ms][2] = Ahi32[aw + 4];    // k+8
                ahi[ms][3] = Ahi32[aw + 164];
                alo[ms][0] = Alo32[aw];
                alo[ms][1] = Alo32[aw + 160];
                alo[ms][2] = Alo32[aw + 4];
                alo[ms][3] = Alo32[aw + 164];
            }
            uint32_t bhi[4][2], blo[4][2];
#pragma unroll
            for (int ns = 0; ns < 4; ns++) {
                const int bw = (s * 8 + c) * 136 + wn * 32 + ns * 8 + g;
                bhi[ns][0] = Bhi32[bw];        // (k=2c:2c+1,   n=g)
                bhi[ns][1] = Bhi32[bw + 544];  // (k=2c+8:2c+9) +4 rows * 136
                blo[ns][0] = Blo32[bw];
                blo[ns][1] = Blo32[bw + 544];
            }
#pragma unroll
            for (int ms = 0; ms < 4; ms++)
#pragma unroll
                for (int ns = 0; ns < 4; ns++) {
                    mma_f16(Cacc[ms][ns], ahi[ms], bhi[ns]);
                    mma_f16(Cacc[ms][ns], ahi[ms], blo[ns]);
                    mma_f16(Cacc[ms][ns], alo[ms], bhi[ns]);
                }
        }
        __syncthreads();

        if (t + 1 < NKT) {
#pragma unroll
            for (int i = 0; i < 4; i++) store_a(i, aReg[i]);
#pragma unroll
            for (int i = 0; i < 4; i++) store_b(i, bReg[i]);
            __syncthreads();
        }
    }

    // ---- epilogue ----
#pragma unroll
    for (int ms = 0; ms < 4; ms++) {
        const int m = m0 + wm * 64 + ms * 16 + g;       // and m+8
#pragma unroll
        for (int ns = 0; ns < 4; ns++) {
            const int n = n0 + wn * 32 + ns * 8 + 2 * c;
            if (QKV) {
                int proj = n / 768;
                int rem  = n - proj * 768;
                int h = rem >> 6, d = rem & 63;
                const float* bias = ((proj == 0) ? bq : (proj == 1) ? bk : bv) + h * D_;
                float* out = (proj == 0) ? g_q : (proj == 1) ? g_k : g_v;
                float b0 = bias[d], b1 = bias[d + 1];
                int bb = m >> 10, s = m & (S_ - 1);
                float* r0 = out + (((size_t)(bb * H_ + h)) * S_ + s) * D_ + d;
                float* r1 = r0 + 8 * D_;
                *(float2*)r0 = make_float2(Cacc[ms][ns][0] + b0,
                                           Cacc[ms][ns][1] + b1);
                *(float2*)r1 = make_float2(Cacc[ms][ns][2] + b0,
                                           Cacc[ms][ns][3] + b1);
            } else {
                float b0 = bo[n], b1 = bo[n + 1];
                float* r0 = dout + (size_t)m * E_ + n;
                float* r1 = r0 + (size_t)8 * E_;
                *(float2*)r0 = make_float2(Cacc[ms][ns][0] + b0,
                                           Cacc[ms][ns][1] + b1);
                *(float2*)r1 = make_float2(Cacc[ms][ns][2] + b0,
                                           Cacc[ms][ns][3] + b1);
            }
        }
    }
}

// ---------------------------------------------------------------------------
// Kernel 2: flash attention (fp32, non-causal) — known correct (R12).
// ---------------------------------------------------------------------------
__global__ __launch_bounds__(256)
void attn_kernel_r13()
{
    extern __shared__ float smf[];
    float* QsT = smf;              // [d][qrow]   64*64
    float* KsT = smf + 4096;       // [d][kvrow]  64*64
    float* Vs  = smf + 8192;       // [kvrow][d]  64*64
    float* Ps  = smf + 12288;      // [kvrow][qrow] 64*65

    const int tid = threadIdx.x;
    const int tx = tid & 15, ty = tid >> 4;
    const int bh = blockIdx.y;
    const int s0 = blockIdx.x * 64;
    const int b = bh / H_;
    const int h = bh - b * H_;

    const float* Q = g_q + (size_t)bh * S_ * D_;
    const float* K = g_k + (size_t)bh * S_ * D_;
    const float* V = g_v + (size_t)bh * S_ * D_;

#pragma unroll
    for (int p = 0; p < 4; p++) {
        int fid = p * 256 + tid;
        int row = fid >> 4;
        int dq  = (fid & 15) * 4;
        float4 qv = *(const float4*)&Q[(size_t)(s0 + row) * D_ + dq];
        QsT[(dq + 0) * 64 + row] = qv.x;
        QsT[(dq + 1) * 64 + row] = qv.y;
        QsT[(dq + 2) * 64 + row] = qv.z;
        QsT[(dq + 3) * 64 + row] = qv.w;
    }

    float m_i[4], l_i[4], o[4][4];
#pragma unroll
    for (int i = 0; i < 4; i++) {
        m_i[i] = -1e30f; l_i[i] = 0.f;
#pragma unroll
        for (int j = 0; j < 4; j++) o[i][j] = 0.f;
    }

    for (int t0 = 0; t0 < S_; t0 += 64) {
#pragma unroll
        for (int p = 0; p < 4; p++) {
            int fid = p * 256 + tid;
            int row = fid >> 4;
            int dq  = (fid & 15) * 4;
            float4 kv4 = *(const float4*)&K[(size_t)(t0 + row) * D_ + dq];
            KsT[(dq + 0) * 64 + row] = kv4.x;
            KsT[(dq + 1) * 64 + row] = kv4.y;
            KsT[(dq + 2) * 64 + row] = kv4.z;
            KsT[(dq + 3) * 64 + row] = kv4.w;
            *(float4*)&Vs[row * 64 + dq] =
                *(const float4*)&V[(size_t)(t0 + row) * D_ + dq];
        }
        __syncthreads();

        float sc[4][4] = {};
#pragma unroll
        for (int kd = 0; kd < 64; kd++) {
            float4 a4 = *(const float4*)&QsT[kd * 64 + ty * 4];
            float4 b4 = *(const float4*)&KsT[kd * 64 + tx * 4];
            float a[4] = {a4.x, a4.y, a4.z, a4.w};
            float bb[4] = {b4.x, b4.y, b4.z, b4.w};
#pragma unroll
            for (int i = 0; i < 4; i++)
#pragma unroll
                for (int j = 0; j < 4; j++)
                    sc[i][j] += a[i] * bb[j];
        }

#pragma unroll
        for (int i = 0; i < 4; i++) {
            float mx = -1e30f;
#pragma unroll
            for (int j = 0; j < 4; j++) {
                sc[i][j] *= 0.125f;
                mx = fmaxf(mx, sc[i][j]);
            }
#pragma unroll
            for (int off = 8; off > 0; off >>= 1)
                mx = fmaxf(mx, __shfl_xor_sync(0xffffffffu, mx, off));
            float mnew = fmaxf(m_i[i], mx);
            float corr = __expf(m_i[i] - mnew);
            float rs = 0.f;
#pragma unroll
            for (int j = 0; j < 4; j++) {
                float p = __expf(sc[i][j] - mnew);
                Ps[(tx * 4 + j) * 65 + ty * 4 + i] = p;
                rs += p;
            }
#pragma unroll
            for (int off = 8; off > 0; off >>= 1)
                rs += __shfl_xor_sync(0xffffffffu, rs, off);
            l_i[i] = l_i[i] * corr + rs;
            m_i[i] = mnew;
#pragma unroll
            for (int j = 0; j < 4; j++) o[i][j] *= corr;
        }
        __syncthreads();

#pragma unroll
        for (int kd = 0; kd < 64; kd++) {
            float pr[4];
#pragma unroll
            for (int i = 0; i < 4; i++)
                pr[i] = Ps[kd * 65 + ty * 4 + i];
            float4 v4 = *(const float4*)&Vs[kd * 64 + tx * 4];
            float vv[4] = {v4.x, v4.y, v4.z, v4.w};
#pragma unroll
            for (int i = 0; i < 4; i++)
#pragma unroll
                for (int j = 0; j < 4; j++)
                    o[i][j] += pr[i] * vv[j];
        }
        __syncthreads();
    }

#pragma unroll
    for (int i = 0; i < 4; i++) {
        float inv = 1.f / l_i[i];
        int qr = s0 + ty * 4 + i;
        float* row = g_x + ((size_t)b * S_ + qr) * E_ + h * D_;
        float4 ov = make_float4(o[i][0] * inv, o[i][1] * inv,
                                o[i][2] * inv, o[i][3] * inv);
        *(float4*)&row[tx * 4] = ov;
    }
}

// ---------------------------------------------------------------------------

extern "C" void kernel_launch(void* const* d_in, const int* in_sizes, int n_in,
                              void* d_out, int out_size)
{
    const float* hid = (const float*)d_in[0];
    const float* Wq  = (const float*)d_in[1];
    const float* Wk  = (const float*)d_in[2];
    const float* Wv  = (const float*)d_in[3];
    const float* bq  = (const float*)d_in[4];
    const float* bk  = (const float*)d_in[5];
    const float* bv  = (const float*)d_in[6];
    const float* Wo  = (const float*)d_in[7];
    const float* bo  = (const float*)d_in[8];
    float* out = (float*)d_out;

    const int attn_smem = (3 * 64 * 64 + 64 * 65) * (int)sizeof(float); // 65792
    cudaFuncSetAttribute(attn_kernel_r13,
                         cudaFuncAttributeMaxDynamicSharedMemorySize, attn_smem);

    // 1) fused QKV projection (fp16 hi/lo HMMA): N = 3*H*D = 2304
    gemm_hl_r13<true><<<dim3(M_ / 128, 2304 / 128), 256>>>(
        hid, Wq, Wk, Wv, bq, bk, bv, nullptr, nullptr, nullptr);

    // 2) attention (fp32)
    attn_kernel_r13<<<dim3(S_ / 64, B_ * H_), 256, attn_smem>>>();

    // 3) output projection (fp16 hi/lo HMMA): A = g_x bound in-kernel
    gemm_hl_r13<false><<<dim3(M_ / 128, 768 / 128), 256>>>(
        nullptr, nullptr, nullptr, nullptr, nullptr, nullptr, nullptr,
        Wo, bo, out);
}

// round 14
// speedup vs baseline: 2.4743x; 1.6596x over previous
#include <cuda_runtime.h>
#include <cuda_fp16.h>
#include <cstdint>

#define B_ 8
#define S_ 1024
#define E_ 768
#define H_ 12
#define D_ 64
#define M_ (B_*S_)   // 8192

// ---------------------------------------------------------------------------
// Scratch (allocations are forbidden; use device globals)
// NOTE: device globals must ONLY be referenced inside device code (GB300
// HMM/ATS silently reads the host shadow symbol otherwise — R6-R11 bug).
// ---------------------------------------------------------------------------
__device__ float g_q[B_*H_*S_*D_];
__device__ float g_k[B_*H_*S_*D_];
__device__ float g_v[B_*H_*S_*D_];
__device__ float g_x[B_*S_*E_];   // attention output, head-concatenated [B,S,E]

// ---------------------------------------------------------------------------
// fp16 m16n8k16 MMA (PTX ISA layouts, g = lane>>2, c = lane&3):
//   A regs (row-major 16x16): a0=(g, 2c:2c+1)  a1=(g+8, 2c:2c+1)
//                             a2=(g, 2c+8:2c+9) a3=(g+8, 2c+8:2c+9)
//   B regs (col-major 16x8):  b0=(k=2c:2c+1, n=g)  b1=(k=2c+8:2c+9, n=g)
//   C regs (16x8 fp32): c0,c1=(g,2c),(g,2c+1); c2,c3=(g+8,2c),(g+8,2c+1)
// ---------------------------------------------------------------------------
__device__ __forceinline__ void mma_f16(float c[4], const uint32_t a[4],
                                        const uint32_t b[2]) {
    asm volatile(
        "mma.sync.aligned.m16n8k16.row.col.f32.f16.f16.f32 "
        "{%0,%1,%2,%3}, {%4,%5,%6,%7}, {%8,%9}, {%0,%1,%2,%3};"
        : "+f"(c[0]), "+f"(c[1]), "+f"(c[2]), "+f"(c[3])
        : "r"(a[0]), "r"(a[1]), "r"(a[2]), "r"(a[3]), "r"(b[0]), "r"(b[1]));
}

__device__ __forceinline__ void split_f16(float x, __half& hi, __half& lo) {
    hi = __float2half_rn(x);
    lo = __float2half_rn(x - __half2float(hi));
}

// Fast exp on the fma/alu pipes (avoids the MUFU rt-8 bottleneck).
// exp(x) = 2^(x*log2e); degree-5 Taylor on the fractional part.
// |rel err| <= ~2.4e-6 for any x <= 0 (clamped at -120 in exponent space).
__device__ __forceinline__ float fexp(float x) {
    float y = fmaxf(x * 1.44269504f, -120.f);
    int   n = __float2int_rn(y);
    float f = y - (float)n;
    float t = f * 0.69314718f;
    float p = 1.f + t * (1.f + t * (0.5f + t * (0.16666667f +
              t * (0.04166667f + t * 0.00833333f))));
    return p * __int_as_float((n + 127) << 23);
}

// ---------------------------------------------------------------------------
// GEMM (unchanged from R13, renamed): fp32-accurate via fp16 hi/lo HMMA.
// ---------------------------------------------------------------------------
#define NKT 24   // 768/32

template <bool QKV>
__global__ __launch_bounds__(256, 1)
void gemm_hl_r14(const float* __restrict__ AsrcArg,
                 const float* __restrict__ Wq, const float* __restrict__ Wk,
                 const float* __restrict__ Wv,
                 const float* __restrict__ bq, const float* __restrict__ bk,
                 const float* __restrict__ bv,
                 const float* __restrict__ Wo, const float* __restrict__ bo,
                 float* __restrict__ dout)
{
    __shared__ __align__(16) __half Ahi[128 * 40];
    __shared__ __align__(16) __half Alo[128 * 40];
    __shared__ __align__(16) __half Bhi[16 * 272];
    __shared__ __align__(16) __half Blo[16 * 272];

    const float* Asrc = QKV ? AsrcArg : (const float*)g_x;

    const int tid  = threadIdx.x;
    const int wid  = tid >> 5, lane = tid & 31;
    const int g    = lane >> 2, c = lane & 3;
    const int wm   = wid >> 2;
    const int wn   = wid & 3;

    const int m0 = blockIdx.x * 128;
    const int n0 = blockIdx.y * 128;

    const float* aptr[4];
    int arow[4], ac4[4];
#pragma unroll
    for (int i = 0; i < 4; i++) {
        int f = tid + i * 256;
        arow[i] = f >> 3;
        ac4[i]  = f & 7;
        aptr[i] = Asrc + (size_t)(m0 + arow[i]) * E_ + ac4[i] * 4;
    }
    const float* bptr[4];
    int bkr[4], bn[4];
#pragma unroll
    for (int i = 0; i < 4; i++) {
        int f = tid + i * 256;
        bkr[i] = f >> 5;
        bn[i]  = (f & 31) * 4;
        int n  = n0 + bn[i];
        if (QKV) {
            int proj = n / 768;
            int rem  = n - proj * 768;
            int h = rem >> 6, d = rem & 63;
            const float* W = (proj == 0) ? Wq : (proj == 1) ? Wk : Wv;
            bptr[i] = W + (size_t)h * E_ * D_ + (size_t)bkr[i] * D_ + d;
        } else {
            bptr[i] = Wo + (size_t)bkr[i] * E_ + n;
        }
    }
    const int badv = QKV ? 32 * D_ : 32 * E_;

    float Cacc[4][4][4];
#pragma unroll
    for (int ms = 0; ms < 4; ms++)
#pragma unroll
        for (int ns = 0; ns < 4; ns++)
#pragma unroll
            for (int r = 0; r < 4; r++) Cacc[ms][ns][r] = 0.f;

    float4 aReg[4], bReg[4];

    auto store_a = [&](int i, const float4& v) {
        __half h0, l0, h1, l1, h2, l2, h3, l3;
        split_f16(v.x, h0, l0); split_f16(v.y, h1, l1);
        split_f16(v.z, h2, l2); split_f16(v.w, h3, l3);
        __half* ah = &Ahi[arow[i] * 40 + ac4[i] * 4];
        __half* al = &Alo[arow[i] * 40 + ac4[i] * 4];
        *(__half2*)&ah[0] = __halves2half2(h0, h1);
        *(__half2*)&ah[2] = __halves2half2(h2, h3);
        *(__half2*)&al[0] = __halves2half2(l0, l1);
        *(__half2*)&al[2] = __halves2half2(l2, l3);
    };
    auto store_b = [&](int i, const float4& v) {
        const int base = (bkr[i] >> 1) * 272 + bn[i] * 2 + (bkr[i] & 1);
        float xs[4] = {v.x, v.y, v.z, v.w};
#pragma unroll
        for (int j = 0; j < 4; j++) {
            __half h, l;
            split_f16(xs[j], h, l);
            Bhi[base + j * 2] = h;
            Blo[base + j * 2] = l;
        }
    };

#pragma unroll
    for (int i = 0; i < 4; i++) aReg[i] = *(const float4*)aptr[i];
#pragma unroll
    for (int i = 0; i < 4; i++) bReg[i] = *(const float4*)bptr[i];
#pragma unroll
    for (int i = 0; i < 4; i++) store_a(i, aReg[i]);
#pragma unroll
    for (int i = 0; i < 4; i++) store_b(i, bReg[i]);
    __syncthreads();

    const uint32_t* Ahi32 = (const uint32_t*)Ahi;
    const uint32_t* Alo32 = (const uint32_t*)Alo;
    const uint32_t* Bhi32 = (const uint32_t*)Bhi;
    const uint32_t* Blo32 = (const uint32_t*)Blo;

    for (int t = 0; t < NKT; t++) {
        if (t + 1 < NKT) {
#pragma unroll
            for (int i = 0; i < 4; i++) {
                aptr[i] += 32;
                aReg[i] = *(const float4*)aptr[i];
            }
#pragma unroll
            for (int i = 0; i < 4; i++) {
                bptr[i] += badv;
                bReg[i] = *(const float4*)bptr[i];
            }
        }

#pragma unroll
        for (int s = 0; s < 2; s++) {
            uint32_t ahi[4][4], alo[4][4];
#pragma unroll
            for (int ms = 0; ms < 4; ms++) {
                const int aw = (wm * 64 + ms * 16 + g) * 20 + s * 8 + c;
                ahi[ms][0] = Ahi32[aw];
                ahi[ms][1] = Ahi32[aw + 160];
                ahi[ms][2] = Ahi32[aw + 4];
                ahi[ms][3] = Ahi32[aw + 164];
                alo[ms][0] = Alo32[aw];
                alo[ms][1] = Alo32[aw + 160];
                alo[ms][2] = Alo32[aw + 4];
                alo[ms][3] = Alo32[aw + 164];
            }
            uint32_t bhi[4][2], blo[4][2];
#pragma unroll
            for (int ns = 0; ns < 4; ns++) {
                const int bw = (s * 8 + c) * 136 + wn * 32 + ns * 8 + g;
                bhi[ns][0] = Bhi32[bw];
                bhi[ns][1] = Bhi32[bw + 544];
                blo[ns][0] = Blo32[bw];
                blo[ns][1] = Blo32[bw + 544];
            }
#pragma unroll
            for (int ms = 0; ms < 4; ms++)
#pragma unroll
                for (int ns = 0; ns < 4; ns++) {
                    mma_f16(Cacc[ms][ns], ahi[ms], bhi[ns]);
                    mma_f16(Cacc[ms][ns], ahi[ms], blo[ns]);
                    mma_f16(Cacc[ms][ns], alo[ms], bhi[ns]);
                }
        }
        __syncthreads();

        if (t + 1 < NKT) {
#pragma unroll
            for (int i = 0; i < 4; i++) store_a(i, aReg[i]);
#pragma unroll
            for (int i = 0; i < 4; i++) store_b(i, bReg[i]);
            __syncthreads();
        }
    }

#pragma unroll
    for (int ms = 0; ms < 4; ms++) {
        const int m = m0 + wm * 64 + ms * 16 + g;
#pragma unroll
        for (int ns = 0; ns < 4; ns++) {
            const int n = n0 + wn * 32 + ns * 8 + 2 * c;
            if (QKV) {
                int proj = n / 768;
                int rem  = n - proj * 768;
                int h = rem >> 6, d = rem & 63;
                const float* bias = ((proj == 0) ? bq : (proj == 1) ? bk : bv) + h * D_;
                float* out = (proj == 0) ? g_q : (proj == 1) ? g_k : g_v;
                float b0 = bias[d], b1 = bias[d + 1];
                int bb = m >> 10, s = m & (S_ - 1);
                float* r0 = out + (((size_t)(bb * H_ + h)) * S_ + s) * D_ + d;
                float* r1 = r0 + 8 * D_;
                *(float2*)r0 = make_float2(Cacc[ms][ns][0] + b0, Cacc[ms][ns][1] + b1);
                *(float2*)r1 = make_float2(Cacc[ms][ns][2] + b0, Cacc[ms][ns][3] + b1);
            } else {
                float b0 = bo[n], b1 = bo[n + 1];
                float* r0 = dout + (size_t)m * E_ + n;
                float* r1 = r0 + (size_t)8 * E_;
                *(float2*)r0 = make_float2(Cacc[ms][ns][0] + b0, Cacc[ms][ns][1] + b1);
                *(float2*)r1 = make_float2(Cacc[ms][ns][2] + b0, Cacc[ms][ns][3] + b1);
            }
        }
    }
}

// ---------------------------------------------------------------------------
// HMMA flash attention. Block = 128 Q rows of one (b,h); 8 warps, each warp
// owns 16 Q rows (m16) x full KV width. KV tiles of 128 rows.
//   QK^T: hi/lo 3-term (QhKh + QhKl + QlKh); K smem k-paired along d,
//         [32 dpairs][136 half2] stride -> fragment banks 8c+g: CF.
//   PV:   hi/lo 3-term; V smem k-paired along kv rows,
//         [64 kvpairs][72 half2] stride  -> fragment banks 8c+g: CF.
//   P: QK^T C-fragment == PV A-fragment (register-only conversion).
//   softmax: rows live in one quad -> 2 shuffles; exp on fma pipe (fexp).
// Smem: Khi,Klo 4352 words each; Vhi,Vlo 4608 words each = 71680 B dynamic.
// ---------------------------------------------------------------------------
__global__ __launch_bounds__(256, 1)
void attn_hmma_r14()
{
    extern __shared__ uint32_t sm2[];
    uint32_t* Khi = sm2;                 // [32][136] half2
    uint32_t* Klo = sm2 + 4352;
    uint32_t* Vhi = sm2 + 8704;          // [64][72] half2
    uint32_t* Vlo = sm2 + 13312;

    const int tid  = threadIdx.x;
    const int wid  = tid >> 5, lane = tid & 31;
    const int g    = lane >> 2, c = lane & 3;
    const int bh   = blockIdx.y;
    const int q0   = blockIdx.x * 128 + wid * 16;

    const float* Q = g_q + (size_t)bh * S_ * D_;
    const float* K = g_k + (size_t)bh * S_ * D_;
    const float* V = g_v + (size_t)bh * S_ * D_;

    // ---- Q A-fragments (hi/lo), loaded once ----
    uint32_t qhi[4][4], qlo[4][4];
#pragma unroll
    for (int s = 0; s < 4; s++) {
        float2 x0 = *(const float2*)&Q[(size_t)(q0 + g    ) * D_ + s * 16 + 2 * c];
        float2 x1 = *(const float2*)&Q[(size_t)(q0 + g + 8) * D_ + s * 16 + 2 * c];
        float2 x2 = *(const float2*)&Q[(size_t)(q0 + g    ) * D_ + s * 16 + 8 + 2 * c];
        float2 x3 = *(const float2*)&Q[(size_t)(q0 + g + 8) * D_ + s * 16 + 8 + 2 * c];
        float2 xs[4] = {x0, x1, x2, x3};
#pragma unroll
        for (int r = 0; r < 4; r++) {
            __half h0, l0, h1, l1;
            split_f16(xs[r].x, h0, l0); split_f16(xs[r].y, h1, l1);
            __half2 hh = __halves2half2(h0, h1);
            __half2 ll = __halves2half2(l0, l1);
            qhi[s][r] = *(uint32_t*)&hh;
            qlo[s][r] = *(uint32_t*)&ll;
        }
    }

    float m0r = -1e30f, m1r = -1e30f, l0r = 0.f, l1r = 0.f;
    float Oa[8][4];
#pragma unroll
    for (int ns = 0; ns < 8; ns++)
#pragma unroll
        for (int r = 0; r < 4; r++) Oa[ns][r] = 0.f;

    for (int t0 = 0; t0 < S_; t0 += 128) {
        __syncthreads();   // previous tile's smem reads done
        // ---- stage K tile: lanes map to consecutive kv rows ----
#pragma unroll
        for (int i = 0; i < 8; i++) {
            int f = i * 256 + tid;
            int kr = f & 127, d4 = f >> 7;          // d4: 0..15
            float4 kv = *(const float4*)&K[(size_t)(t0 + kr) * D_ + d4 * 4];
            __half h0, l0, h1, l1, h2, l2, h3, l3;
            split_f16(kv.x, h0, l0); split_f16(kv.y, h1, l1);
            split_f16(kv.z, h2, l2); split_f16(kv.w, h3, l3);
            __half2 a = __halves2half2(h0, h1), b = __halves2half2(h2, h3);
            __half2 e = __halves2half2(l0, l1), d = __halves2half2(l2, l3);
            Khi[(2 * d4 + 0) * 136 + kr] = *(uint32_t*)&a;
            Khi[(2 * d4 + 1) * 136 + kr] = *(uint32_t*)&b;
            Klo[(2 * d4 + 0) * 136 + kr] = *(uint32_t*)&e;
            Klo[(2 * d4 + 1) * 136 + kr] = *(uint32_t*)&d;
        }
        // ---- stage V tile: coalesced row loads, half-stores k-paired ----
        {
            __half* VhiH = (__half*)Vhi;
            __half* VloH = (__half*)Vlo;
#pragma unroll
            for (int i = 0; i < 8; i++) {
                int kr = i * 16 + (tid >> 4);
                int n4 = tid & 15;
                float4 vv = *(const float4*)&V[(size_t)(t0 + kr) * D_ + n4 * 4];
                float xs[4] = {vv.x, vv.y, vv.z, vv.w};
                int base = ((kr >> 1) * 72 + n4 * 4) * 2 + (kr & 1);
#pragma unroll
                for (int j = 0; j < 4; j++) {
                    __half h, l;
                    split_f16(xs[j], h, l);
                    VhiH[base + j * 2] = h;
                    VloH[base + j * 2] = l;
                }
            }
        }
        __syncthreads();

        // ---- S = Q K^T (3-term hi/lo) ----
        float Sa[16][4];
#pragma unroll
        for (int ns = 0; ns < 16; ns++)
#pragma unroll
            for (int r = 0; r < 4; r++) Sa[ns][r] = 0.f;
#pragma unroll
        for (int s = 0; s < 4; s++) {
#pragma unroll
            for (int ns = 0; ns < 16; ns++) {
                uint32_t bhi[2], blo[2];
                const int bw = (s * 8 + c) * 136 + ns * 8 + g;
                bhi[0] = Khi[bw]; bhi[1] = Khi[bw + 544];
                blo[0] = Klo[bw]; blo[1] = Klo[bw + 544];
                mma_f16(Sa[ns], qhi[s], bhi);
                mma_f16(Sa[ns], qhi[s], blo);
                mma_f16(Sa[ns], qlo[s], bhi);
            }
        }

        // ---- online softmax (rows g and g+8 live in this quad) ----
        float mx0 = -1e30f, mx1 = -1e30f;
#pragma unroll
        for (int ns = 0; ns < 16; ns++) {
            Sa[ns][0] *= 0.125f; Sa[ns][1] *= 0.125f;
            Sa[ns][2] *= 0.125f; Sa[ns][3] *= 0.125f;
            mx0 = fmaxf(mx0, fmaxf(Sa[ns][0], Sa[ns][1]));
            mx1 = fmaxf(mx1, fmaxf(Sa[ns][2], Sa[ns][3]));
        }
        mx0 = fmaxf(mx0, __shfl_xor_sync(0xffffffffu, mx0, 1));
        mx0 = fmaxf(mx0, __shfl_xor_sync(0xffffffffu, mx0, 2));
        mx1 = fmaxf(mx1, __shfl_xor_sync(0xffffffffu, mx1, 1));
        mx1 = fmaxf(mx1, __shfl_xor_sync(0xffffffffu, mx1, 2));
        float mn0 = fmaxf(m0r, mx0), mn1 = fmaxf(m1r, mx1);
        float corr0 = fexp(m0r - mn0), corr1 = fexp(m1r - mn1);
        float sum0 = 0.f, sum1 = 0.f;
#pragma unroll
        for (int ns = 0; ns < 16; ns++) {
            Sa[ns][0] = fexp(Sa[ns][0] - mn0); sum0 += Sa[ns][0];
            Sa[ns][1] = fexp(Sa[ns][1] - mn0); sum0 += Sa[ns][1];
            Sa[ns][2] = fexp(Sa[ns][2] - mn1); sum1 += Sa[ns][2];
            Sa[ns][3] = fexp(Sa[ns][3] - mn1); sum1 += Sa[ns][3];
        }
        sum0 += __shfl_xor_sync(0xffffffffu, sum0, 1);
        sum0 += __shfl_xor_sync(0xffffffffu, sum0, 2);
        sum1 += __shfl_xor_sync(0xffffffffu, sum1, 1);
        sum1 += __shfl_xor_sync(0xffffffffu, sum1, 2);
        l0r = l0r * corr0 + sum0; m0r = mn0;
        l1r = l1r * corr1 + sum1; m1r = mn1;
#pragma unroll
        for (int ns = 0; ns < 8; ns++) {
            Oa[ns][0] *= corr0; Oa[ns][1] *= corr0;
            Oa[ns][2] *= corr1; Oa[ns][3] *= corr1;
        }

        // ---- P -> A fragments (register-only, hi/lo) ----
        uint32_t phi[8][4], plo[8][4];
#pragma unroll
        for (int s = 0; s < 8; s++) {
            float v[4][2] = {{Sa[2*s][0],   Sa[2*s][1]},
                             {Sa[2*s][2],   Sa[2*s][3]},
                             {Sa[2*s+1][0], Sa[2*s+1][1]},
                             {Sa[2*s+1][2], Sa[2*s+1][3]}};
#pragma unroll
            for (int r = 0; r < 4; r++) {
                __half2 hh = __floats2half2_rn(v[r][0], v[r][1]);
                float2 fb = __half22float2(hh);
                __half2 ll = __floats2half2_rn(v[r][0] - fb.x, v[r][1] - fb.y);
                phi[s][r] = *(uint32_t*)&hh;
                plo[s][r] = *(uint32_t*)&ll;
            }
        }

        // ---- O += P V (3-term hi/lo) ----
#pragma unroll
        for (int s = 0; s < 8; s++) {
#pragma unroll
            for (int ns = 0; ns < 8; ns++) {
                uint32_t bhi[2], blo[2];
                const int bw = (s * 8 + c) * 72 + ns * 8 + g;
                bhi[0] = Vhi[bw]; bhi[1] = Vhi[bw + 288];
                blo[0] = Vlo[bw]; blo[1] = Vlo[bw + 288];
                mma_f16(Oa[ns], phi[s], bhi);
                mma_f16(Oa[ns], phi[s], blo);
                mma_f16(Oa[ns], plo[s], bhi);
            }
        }
    }

    // ---- epilogue: write head-concatenated g_x ----
    const float inv0 = 1.f / l0r, inv1 = 1.f / l1r;
    const int b = bh / H_, h = bh - b * H_;
    float* r0 = g_x + ((size_t)b * S_ + q0 + g    ) * E_ + h * 64 + 2 * c;
    float* r1 = g_x + ((size_t)b * S_ + q0 + g + 8) * E_ + h * 64 + 2 * c;
#pragma unroll
    for (int ns = 0; ns < 8; ns++) {
        *(float2*)(r0 + ns * 8) = make_float2(Oa[ns][0] * inv0, Oa[ns][1] * inv0);
        *(float2*)(r1 + ns * 8) = make_float2(Oa[ns][2] * inv1, Oa[ns][3] * inv1);
    }
}

// ---------------------------------------------------------------------------

extern "C" void kernel_launch(void* const* d_in, const int* in_sizes, int n_in,
                              void* d_out, int out_size)
{
    const float* hid = (const float*)d_in[0];
    const float* Wq  = (const float*)d_in[1];
    const float* Wk  = (const float*)d_in[2];
    const float* Wv  = (const float*)d_in[3];
    const float* bq  = (const float*)d_in[4];
    const float* bk  = (const float*)d_in[5];
    const float* bv  = (const float*)d_in[6];
    const float* Wo  = (const float*)d_in[7];
    const float* bo  = (const float*)d_in[8];
    float* out = (float*)d_out;

    const int attn_smem = 71680;
    cudaFuncSetAttribute(attn_hmma_r14,
                         cudaFuncAttributeMaxDynamicSharedMemorySize, attn_smem);

    // 1) fused QKV projection (fp16 hi/lo HMMA): N = 2304
    gemm_hl_r14<true><<<dim3(M_ / 128, 2304 / 128), 256>>>(
        hid, Wq, Wk, Wv, bq, bk, bv, nullptr, nullptr, nullptr);

    // 2) attention (fp16 hi/lo HMMA + fma-pipe exp)
    attn_hmma_r14<<<dim3(S_ / 128, B_ * H_), 256, attn_smem>>>();

    // 3) output projection (A = g_x bound in-kernel)
    gemm_hl_r14<false><<<dim3(M_ / 128, 768 / 128), 256>>>(
        nullptr, nullptr, nullptr, nullptr, nullptr, nullptr, nullptr,
        Wo, bo, out);
}

// round 15
// speedup vs baseline: 2.8851x; 1.1660x over previous
#include <cuda_runtime.h>
#include <cuda_fp16.h>
#include <cstdint>

#define B_ 8
#define S_ 1024
#define E_ 768
#define H_ 12
#define D_ 64
#define M_ (B_*S_)   // 8192

// ---------------------------------------------------------------------------
// Scratch (allocations forbidden; device globals). NEVER pass these as kernel
// args from host (GB300 HMM/ATS silently reads the host shadow — R6-R11 bug).
// ---------------------------------------------------------------------------
__device__ float g_q[B_*H_*S_*D_];
__device__ float g_k[B_*H_*S_*D_];
__device__ float g_v[B_*H_*S_*D_];
__device__ float g_x[B_*S_*E_];       // attention output [B,S,E] fp32

// pre-split fp16 hi/lo operands
__device__ __half  g_hidh[M_*E_],  g_hidl[M_*E_];     // A for qkv GEMM
__device__ __half  g_xh[M_*E_],    g_xl[M_*E_];       // A for proj GEMM
__device__ __half2 g_wh[(E_/2)*2304], g_wl[(E_/2)*2304];   // B qkv, k-paired
__device__ __half2 g_woh[(E_/2)*E_],  g_wol[(E_/2)*E_];    // B proj, k-paired

// ---------------------------------------------------------------------------
// Helpers
// ---------------------------------------------------------------------------
__device__ __forceinline__ uint32_t smem_u32(const void* p) {
    uint32_t a;
    asm("{ .reg .u64 t; cvta.to.shared.u64 t, %1; cvt.u32.u64 %0, t; }"
        : "=r"(a) : "l"(p));
    return a;
}
__device__ __forceinline__ void mma_f16(float c[4], const uint32_t a[4],
                                        const uint32_t b[2]) {
    asm volatile(
        "mma.sync.aligned.m16n8k16.row.col.f32.f16.f16.f32 "
        "{%0,%1,%2,%3}, {%4,%5,%6,%7}, {%8,%9}, {%0,%1,%2,%3};"
        : "+f"(c[0]), "+f"(c[1]), "+f"(c[2]), "+f"(c[3])
        : "r"(a[0]), "r"(a[1]), "r"(a[2]), "r"(a[3]), "r"(b[0]), "r"(b[1]));
}
__device__ __forceinline__ void split_f16(float x, __half& hi, __half& lo) {
    hi = __float2half_rn(x);
    lo = __float2half_rn(x - __half2float(hi));
}
// fma-pipe exp (avoids MUFU bottleneck); |rel err| <= ~2.4e-6 for x <= 0.
__device__ __forceinline__ float fexp(float x) {
    float y = fmaxf(x * 1.44269504f, -120.f);
    int   n = __float2int_rn(y);
    float f = y - (float)n;
    float t = f * 0.69314718f;
    float p = 1.f + t * (1.f + t * (0.5f + t * (0.16666667f +
              t * (0.04166667f + t * 0.00833333f))));
    return p * __int_as_float((n + 127) << 23);
}
#define CP_ASYNC16(dst, src) \
    asm volatile("cp.async.cg.shared.global [%0], [%1], 16;" \
        :: "r"(dst), "l"(src) : "memory")
#define CP_COMMIT() asm volatile("cp.async.commit_group;" ::: "memory")

// ---------------------------------------------------------------------------
// Pre-split kernels.
// split_a: fp32 [M_,E_] -> hi/lo fp16 same layout. 4 floats/thread.
// split_b: weights -> k-paired half2 [k2][Ntot] (low half = even k).
// ---------------------------------------------------------------------------
template <bool FROM_HID>
__global__ __launch_bounds__(256)
void split_a_r15(const float* __restrict__ src)
{
    const int idx = blockIdx.x * 256 + threadIdx.x;       // float4 index
    const float4 v = ((const float4*)(FROM_HID ? src : (const float*)g_x))[idx];
    __half h0,l0,h1,l1,h2,l2,h3,l3;
    split_f16(v.x,h0,l0); split_f16(v.y,h1,l1);
    split_f16(v.z,h2,l2); split_f16(v.w,h3,l3);
    __half* dh = FROM_HID ? g_hidh : g_xh;
    __half* dl = FROM_HID ? g_hidl : g_xl;
    __half2 a = __halves2half2(h0,h1), b = __halves2half2(h2,h3);
    __half2 e = __halves2half2(l0,l1), f = __halves2half2(l2,l3);
    ((__half2*)dh)[2*idx]   = a; ((__half2*)dh)[2*idx+1] = b;
    ((__half2*)dl)[2*idx]   = e; ((__half2*)dl)[2*idx+1] = f;
}

template <bool QKV>
__global__ __launch_bounds__(256)
void split_b_r15(const float* __restrict__ Wq, const float* __restrict__ Wk,
                 const float* __restrict__ Wv, const float* __restrict__ Wo)
{
    const int n  = blockIdx.x * 256 + threadIdx.x;
    const int k2 = blockIdx.y;                             // 0..383
    float v0, v1;
    if (QKV) {
        int proj = n / 768, rem = n - proj * 768;
        int h = rem >> 6, d = rem & 63;
        const float* W = (proj == 0) ? Wq : (proj == 1) ? Wk : Wv;
        size_t base = ((size_t)h * E_ + 2 * k2) * D_ + d;
        v0 = W[base]; v1 = W[base + D_];
    } else {
        v0 = Wo[(size_t)(2 * k2) * E_ + n];
        v1 = Wo[(size_t)(2 * k2 + 1) * E_ + n];
    }
    __half h0,l0,h1,l1;
    split_f16(v0,h0,l0); split_f16(v1,h1,l1);
    const int Ntot = QKV ? 2304 : 768;
    __half2* dh = QKV ? g_wh : g_woh;
    __half2* dl = QKV ? g_wl : g_wol;
    dh[(size_t)k2 * Ntot + n] = __halves2half2(h0, h1);    // (even, odd)
    dl[(size_t)k2 * Ntot + n] = __halves2half2(l0, l1);
}

// ---------------------------------------------------------------------------
// GEMM v2: fp32-accurate hi/lo HMMA, pre-split fp16 inputs, cp.async
// double-buffered staging, 2 CTAs/SM.
// Tile 128x128, 256 thr = 8 warps (2m x 4n), warp tile 64x32 (same fragment
// code as R14). Per smem buffer (37888 B): Ahi[128][40]h +0, Alo +10240,
// Bhi[16][136]half2 +20480, Blo +29184. Two buffers = 75776 B dynamic.
// ---------------------------------------------------------------------------
#define CHUNKS 24     // 768/32
#define BUF_BYTES 37888

template <bool QKV>
__global__ __launch_bounds__(256, 2)
void gemm_v2_r15(const float* __restrict__ bq, const float* __restrict__ bk,
                 const float* __restrict__ bv, const float* __restrict__ bo,
                 float* __restrict__ dout)
{
    extern __shared__ char smc[];
    const uint32_t smb = smem_u32(smc);
    const int Ntot = QKV ? 2304 : 768;

    const int tid = threadIdx.x;
    const int wid = tid >> 5, lane = tid & 31;
    const int g = lane >> 2, c = lane & 3;
    const int wm = wid >> 2, wn = wid & 3;
    const int m0 = blockIdx.x * 128, n0 = blockIdx.y * 128;

    const __half*  Ah = QKV ? g_hidh : g_xh;
    const __half*  Al = QKV ? g_hidl : g_xl;
    const __half2* Bh = QKV ? g_wh : g_woh;
    const __half2* Bl = QKV ? g_wl : g_wol;

    // staging descriptors (16B segments)
    const int ar0 = tid >> 2,        as0 = tid & 3;
    const int ar1 = (tid + 256) >> 2, as1 = (tid + 256) & 3;
    const uint32_t adst0 = ar0 * 80 + as0 * 16;
    const uint32_t adst1 = ar1 * 80 + as1 * 16;
    const size_t aoff0 = (size_t)(m0 + ar0) * E_ + as0 * 8;   // halfs
    const size_t aoff1 = (size_t)(m0 + ar1) * E_ + as1 * 8;
    const int br0 = tid >> 5,        bo0 = tid & 31;
    const int br1 = (tid + 256) >> 5, bo1 = (tid + 256) & 31;
    const uint32_t bdst0 = br0 * 544 + bo0 * 16;
    const uint32_t bdst1 = br1 * 544 + bo1 * 16;
    const size_t boff0 = (size_t)br0 * Ntot + n0 + bo0 * 4;   // half2s
    const size_t boff1 = (size_t)br1 * Ntot + n0 + bo1 * 4;

    auto stage = [&](int t, int p) {
        const uint32_t ab = smb + p * BUF_BYTES;
        const int tk = t * 32;                 // A half offset along k
        const size_t bk16 = (size_t)t * 16 * Ntot;
        CP_ASYNC16(ab + adst0,         Ah + aoff0 + tk);
        CP_ASYNC16(ab + adst1,         Ah + aoff1 + tk);
        CP_ASYNC16(ab + 10240 + adst0, Al + aoff0 + tk);
        CP_ASYNC16(ab + 10240 + adst1, Al + aoff1 + tk);
        CP_ASYNC16(ab + 20480 + bdst0, Bh + boff0 + bk16);
        CP_ASYNC16(ab + 20480 + bdst1, Bh + boff1 + bk16);
        CP_ASYNC16(ab + 29184 + bdst0, Bl + boff0 + bk16);
        CP_ASYNC16(ab + 29184 + bdst1, Bl + boff1 + bk16);
        CP_COMMIT();
    };

    float Cacc[4][4][4];
#pragma unroll
    for (int ms = 0; ms < 4; ms++)
#pragma unroll
        for (int ns = 0; ns < 4; ns++)
#pragma unroll
            for (int r = 0; r < 4; r++) Cacc[ms][ns][r] = 0.f;

    stage(0, 0);

    for (int t = 0; t < CHUNKS; t++) {
        const int p = t & 1;
        if (t + 1 < CHUNKS) {
            stage(t + 1, 1 - p);
            asm volatile("cp.async.wait_group 1;" ::: "memory");
        } else {
            asm volatile("cp.async.wait_group 0;" ::: "memory");
        }
        __syncthreads();

        const uint32_t* Ahi32 = (const uint32_t*)(smc + p * BUF_BYTES);
        const uint32_t* Alo32 = Ahi32 + 2560;
        const uint32_t* Bhi32 = Ahi32 + 5120;
        const uint32_t* Blo32 = Ahi32 + 7296;

#pragma unroll
        for (int s = 0; s < 2; s++) {
            uint32_t ahi[4][4], alo[4][4];
#pragma unroll
            for (int ms = 0; ms < 4; ms++) {
                const int aw = (wm * 64 + ms * 16 + g) * 20 + s * 8 + c;
                ahi[ms][0] = Ahi32[aw];
                ahi[ms][1] = Ahi32[aw + 160];
                ahi[ms][2] = Ahi32[aw + 4];
                ahi[ms][3] = Ahi32[aw + 164];
                alo[ms][0] = Alo32[aw];
                alo[ms][1] = Alo32[aw + 160];
                alo[ms][2] = Alo32[aw + 4];
                alo[ms][3] = Alo32[aw + 164];
            }
#pragma unroll
            for (int ns = 0; ns < 4; ns++) {
                const int bw = (s * 8 + c) * 136 + wn * 32 + ns * 8 + g;
                uint32_t bh2[2] = {Bhi32[bw], Bhi32[bw + 544]};
                uint32_t bl2[2] = {Blo32[bw], Blo32[bw + 544]};
#pragma unroll
                for (int ms = 0; ms < 4; ms++) {
                    mma_f16(Cacc[ms][ns], ahi[ms], bh2);
                    mma_f16(Cacc[ms][ns], ahi[ms], bl2);
                    mma_f16(Cacc[ms][ns], alo[ms], bh2);
                }
            }
        }
        __syncthreads();
    }

    // ---- epilogue (same as R14) ----
#pragma unroll
    for (int ms = 0; ms < 4; ms++) {
        const int m = m0 + wm * 64 + ms * 16 + g;
#pragma unroll
        for (int ns = 0; ns < 4; ns++) {
            const int n = n0 + wn * 32 + ns * 8 + 2 * c;
            if (QKV) {
                int proj = n / 768;
                int rem  = n - proj * 768;
                int h = rem >> 6, d = rem & 63;
                const float* bias = ((proj == 0) ? bq : (proj == 1) ? bk : bv) + h * D_;
                float* out = (proj == 0) ? g_q : (proj == 1) ? g_k : g_v;
                float b0 = bias[d], b1 = bias[d + 1];
                int bb = m >> 10, s = m & (S_ - 1);
                float* r0 = out + (((size_t)(bb * H_ + h)) * S_ + s) * D_ + d;
                float* r1 = r0 + 8 * D_;
                *(float2*)r0 = make_float2(Cacc[ms][ns][0] + b0, Cacc[ms][ns][1] + b1);
                *(float2*)r1 = make_float2(Cacc[ms][ns][2] + b0, Cacc[ms][ns][3] + b1);
            } else {
                float b0 = bo[n], b1 = bo[n + 1];
                float* r0 = dout + (size_t)m * E_ + n;
                float* r1 = r0 + (size_t)8 * E_;
                *(float2*)r0 = make_float2(Cacc[ms][ns][0] + b0, Cacc[ms][ns][1] + b1);
                *(float2*)r1 = make_float2(Cacc[ms][ns][2] + b0, Cacc[ms][ns][3] + b1);
            }
        }
    }
}

// ---------------------------------------------------------------------------
// HMMA flash attention — unchanged from R14 (proven), renamed.
// ---------------------------------------------------------------------------
__global__ __launch_bounds__(256, 1)
void attn_hmma_r15()
{
    extern __shared__ uint32_t sm2[];
    uint32_t* Khi = sm2;                 // [32][136] half2
    uint32_t* Klo = sm2 + 4352;
    uint32_t* Vhi = sm2 + 8704;          // [64][72] half2
    uint32_t* Vlo = sm2 + 13312;

    const int tid  = threadIdx.x;
    const int wid  = tid >> 5, lane = tid & 31;
    const int g    = lane >> 2, c = lane & 3;
    const int bh   = blockIdx.y;
    const int q0   = blockIdx.x * 128 + wid * 16;

    const float* Q = g_q + (size_t)bh * S_ * D_;
    const float* K = g_k + (size_t)bh * S_ * D_;
    const float* V = g_v + (size_t)bh * S_ * D_;

    uint32_t qhi[4][4], qlo[4][4];
#pragma unroll
    for (int s = 0; s < 4; s++) {
        float2 x0 = *(const float2*)&Q[(size_t)(q0 + g    ) * D_ + s * 16 + 2 * c];
        float2 x1 = *(const float2*)&Q[(size_t)(q0 + g + 8) * D_ + s * 16 + 2 * c];
        float2 x2 = *(const float2*)&Q[(size_t)(q0 + g    ) * D_ + s * 16 + 8 + 2 * c];
        float2 x3 = *(const float2*)&Q[(size_t)(q0 + g + 8) * D_ + s * 16 + 8 + 2 * c];
        float2 xs[4] = {x0, x1, x2, x3};
#pragma unroll
        for (int r = 0; r < 4; r++) {
            __half h0, l0, h1, l1;
            split_f16(xs[r].x, h0, l0); split_f16(xs[r].y, h1, l1);
            __half2 hh = __halves2half2(h0, h1);
            __half2 ll = __halves2half2(l0, l1);
            qhi[s][r] = *(uint32_t*)&hh;
            qlo[s][r] = *(uint32_t*)&ll;
        }
    }

    float m0r = -1e30f, m1r = -1e30f, l0r = 0.f, l1r = 0.f;
    float Oa[8][4];
#pragma unroll
    for (int ns = 0; ns < 8; ns++)
#pragma unroll
        for (int r = 0; r < 4; r++) Oa[ns][r] = 0.f;

    for (int t0 = 0; t0 < S_; t0 += 128) {
        __syncthreads();
#pragma unroll
        for (int i = 0; i < 8; i++) {
            int f = i * 256 + tid;
            int kr = f & 127, d4 = f >> 7;
            float4 kv = *(const float4*)&K[(size_t)(t0 + kr) * D_ + d4 * 4];
            __half h0, l0, h1, l1, h2, l2, h3, l3;
            split_f16(kv.x, h0, l0); split_f16(kv.y, h1, l1);
            split_f16(kv.z, h2, l2); split_f16(kv.w, h3, l3);
            __half2 a = __halves2half2(h0, h1), b = __halves2half2(h2, h3);
            __half2 e = __halves2half2(l0, l1), d = __halves2half2(l2, l3);
            Khi[(2 * d4 + 0) * 136 + kr] = *(uint32_t*)&a;
            Khi[(2 * d4 + 1) * 136 + kr] = *(uint32_t*)&b;
            Klo[(2 * d4 + 0) * 136 + kr] = *(uint32_t*)&e;
            Klo[(2 * d4 + 1) * 136 + kr] = *(uint32_t*)&d;
        }
        {
            __half* VhiH = (__half*)Vhi;
            __half* VloH = (__half*)Vlo;
#pragma unroll
            for (int i = 0; i < 8; i++) {
                int kr = i * 16 + (tid >> 4);
                int n4 = tid & 15;
                float4 vv = *(const float4*)&V[(size_t)(t0 + kr) * D_ + n4 * 4];
                float xs[4] = {vv.x, vv.y, vv.z, vv.w};
                int base = ((kr >> 1) * 72 + n4 * 4) * 2 + (kr & 1);
#pragma unroll
                for (int j = 0; j < 4; j++) {
                    __half h, l;
                    split_f16(xs[j], h, l);
                    VhiH[base + j * 2] = h;
                    VloH[base + j * 2] = l;
                }
            }
        }
        __syncthreads();

        float Sa[16][4];
#pragma unroll
        for (int ns = 0; ns < 16; ns++)
#pragma unroll
            for (int r = 0; r < 4; r++) Sa[ns][r] = 0.f;
#pragma unroll
        for (int s = 0; s < 4; s++) {
#pragma unroll
            for (int ns = 0; ns < 16; ns++) {
                uint32_t bhi[2], blo[2];
                const int bw = (s * 8 + c) * 136 + ns * 8 + g;
                bhi[0] = Khi[bw]; bhi[1] = Khi[bw + 544];
                blo[0] = Klo[bw]; blo[1] = Klo[bw + 544];
                mma_f16(Sa[ns], qhi[s], bhi);
                mma_f16(Sa[ns], qhi[s], blo);
                mma_f16(Sa[ns], qlo[s], bhi);
            }
        }

        float mx0 = -1e30f, mx1 = -1e30f;
#pragma unroll
        for (int ns = 0; ns < 16; ns++) {
            Sa[ns][0] *= 0.125f; Sa[ns][1] *= 0.125f;
            Sa[ns][2] *= 0.125f; Sa[ns][3] *= 0.125f;
            mx0 = fmaxf(mx0, fmaxf(Sa[ns][0], Sa[ns][1]));
            mx1 = fmaxf(mx1, fmaxf(Sa[ns][2], Sa[ns][3]));
        }
        mx0 = fmaxf(mx0, __shfl_xor_sync(0xffffffffu, mx0, 1));
        mx0 = fmaxf(mx0, __shfl_xor_sync(0xffffffffu, mx0, 2));
        mx1 = fmaxf(mx1, __shfl_xor_sync(0xffffffffu, mx1, 1));
        mx1 = fmaxf(mx1, __shfl_xor_sync(0xffffffffu, mx1, 2));
        float mn0 = fmaxf(m0r, mx0), mn1 = fmaxf(m1r, mx1);
        float corr0 = fexp(m0r - mn0), corr1 = fexp(m1r - mn1);
        float sum0 = 0.f, sum1 = 0.f;
#pragma unroll
        for (int ns = 0; ns < 16; ns++) {
            Sa[ns][0] = fexp(Sa[ns][0] - mn0); sum0 += Sa[ns][0];
            Sa[ns][1] = fexp(Sa[ns][1] - mn0); sum0 += Sa[ns][1];
            Sa[ns][2] = fexp(Sa[ns][2] - mn1); sum1 += Sa[ns][2];
            Sa[ns][3] = fexp(Sa[ns][3] - mn1); sum1 += Sa[ns][3];
        }
        sum0 += __shfl_xor_sync(0xffffffffu, sum0, 1);
        sum0 += __shfl_xor_sync(0xffffffffu, sum0, 2);
        sum1 += __shfl_xor_sync(0xffffffffu, sum1, 1);
        sum1 += __shfl_xor_sync(0xffffffffu, sum1, 2);
        l0r = l0r * corr0 + sum0; m0r = mn0;
        l1r = l1r * corr1 + sum1; m1r = mn1;
#pragma unroll
        for (int ns = 0; ns < 8; ns++) {
            Oa[ns][0] *= corr0; Oa[ns][1] *= corr0;
            Oa[ns][2] *= corr1; Oa[ns][3] *= corr1;
        }

        uint32_t phi[8][4], plo[8][4];
#pragma unroll
        for (int s = 0; s < 8; s++) {
            float v[4][2] = {{Sa[2*s][0],   Sa[2*s][1]},
                             {Sa[2*s][2],   Sa[2*s][3]},
                             {Sa[2*s+1][0], Sa[2*s+1][1]},
                             {Sa[2*s+1][2], Sa[2*s+1][3]}};
#pragma unroll
            for (int r = 0; r < 4; r++) {
                __half2 hh = __floats2half2_rn(v[r][0], v[r][1]);
                float2 fb = __half22float2(hh);
                __half2 ll = __floats2half2_rn(v[r][0] - fb.x, v[r][1] - fb.y);
                phi[s][r] = *(uint32_t*)&hh;
                plo[s][r] = *(uint32_t*)&ll;
            }
        }

#pragma unroll
        for (int s = 0; s < 8; s++) {
#pragma unroll
            for (int ns = 0; ns < 8; ns++) {
                uint32_t bhi[2], blo[2];
                const int bw = (s * 8 + c) * 72 + ns * 8 + g;
                bhi[0] = Vhi[bw]; bhi[1] = Vhi[bw + 288];
                blo[0] = Vlo[bw]; blo[1] = Vlo[bw + 288];
                mma_f16(Oa[ns], phi[s], bhi);
                mma_f16(Oa[ns], phi[s], blo);
                mma_f16(Oa[ns], plo[s], bhi);
            }
        }
    }

    const float inv0 = 1.f / l0r, inv1 = 1.f / l1r;
    const int b = bh / H_, h = bh - b * H_;
    float* r0 = g_x + ((size_t)b * S_ + q0 + g    ) * E_ + h * 64 + 2 * c;
    float* r1 = g_x + ((size_t)b * S_ + q0 + g + 8) * E_ + h * 64 + 2 * c;
#pragma unroll
    for (int ns = 0; ns < 8; ns++) {
        *(float2*)(r0 + ns * 8) = make_float2(Oa[ns][0] * inv0, Oa[ns][1] * inv0);
        *(float2*)(r1 + ns * 8) = make_float2(Oa[ns][2] * inv1, Oa[ns][3] * inv1);
    }
}

// ---------------------------------------------------------------------------

extern "C" void kernel_launch(void* const* d_in, const int* in_sizes, int n_in,
                              void* d_out, int out_size)
{
    const float* hid = (const float*)d_in[0];
    const float* Wq  = (const float*)d_in[1];
    const float* Wk  = (const float*)d_in[2];
    const float* Wv  = (const float*)d_in[3];
    const float* bq  = (const float*)d_in[4];
    const float* bk  = (const float*)d_in[5];
    const float* bv  = (const float*)d_in[6];
    const float* Wo  = (const float*)d_in[7];
    const float* bo  = (const float*)d_in[8];
    float* out = (float*)d_out;

    const int attn_smem = 71680;
    const int gemm_smem = 2 * BUF_BYTES;   // 75776
    cudaFuncSetAttribute(attn_hmma_r15,
                         cudaFuncAttributeMaxDynamicSharedMemorySize, attn_smem);
    cudaFuncSetAttribute(gemm_v2_r15<true>,
                         cudaFuncAttributeMaxDynamicSharedMemorySize, gemm_smem);
    cudaFuncSetAttribute(gemm_v2_r15<false>,
                         cudaFuncAttributeMaxDynamicSharedMemorySize, gemm_smem);

    // 0) pre-split inputs to fp16 hi/lo
    split_a_r15<true><<<M_ * E_ / 4 / 256, 256>>>(hid);
    split_b_r15<true><<<dim3(2304 / 256, E_ / 2), 256>>>(Wq, Wk, Wv, nullptr);
    split_b_r15<false><<<dim3(768 / 256, E_ / 2), 256>>>(nullptr, nullptr, nullptr, Wo);

    // 1) fused QKV projection
    gemm_v2_r15<true><<<dim3(M_ / 128, 2304 / 128), 256, gemm_smem>>>(
        bq, bk, bv, nullptr, nullptr);

    // 2) attention
    attn_hmma_r15<<<dim3(S_ / 128, B_ * H_), 256, attn_smem>>>();

    // 3) split attention output, then output projection
    split_a_r15<false><<<M_ * E_ / 4 / 256, 256>>>(nullptr);
    gemm_v2_r15<false><<<dim3(M_ / 128, 768 / 128), 256, gemm_smem>>>(
        nullptr, nullptr, nullptr, bo, out);
}

// round 16
// speedup vs baseline: 3.7008x; 1.2827x over previous
#include <cuda_runtime.h>
#include <cuda_fp16.h>
#include <cstdint>

#define B_ 8
#define S_ 1024
#define E_ 768
#define H_ 12
#define D_ 64
#define M_ (B_*S_)   // 8192

// ---------------------------------------------------------------------------
// Scratch (allocations forbidden; device globals). NEVER pass these as kernel
// args from host (GB300 HMM/ATS silently reads the host shadow — R6-R11 bug).
// ---------------------------------------------------------------------------
__device__ float g_q[B_*H_*S_*D_];
__device__ float g_k[B_*H_*S_*D_];
__device__ float g_v[B_*H_*S_*D_];
__device__ float g_x[B_*S_*E_];       // attention output [B,S,E] fp32

// pre-split operands: A needs hi only (2-term scheme); B needs hi+lo k-paired
__device__ __half  g_hidh[M_*E_];                     // A for qkv GEMM
__device__ __half  g_xh[M_*E_];                       // A for proj GEMM
__device__ __half2 g_wh[(E_/2)*2304], g_wl[(E_/2)*2304];   // B qkv
__device__ __half2 g_woh[(E_/2)*E_],  g_wol[(E_/2)*E_];    // B proj

// ---------------------------------------------------------------------------
// Helpers
// ---------------------------------------------------------------------------
__device__ __forceinline__ uint32_t smem_u32(const void* p) {
    uint32_t a;
    asm("{ .reg .u64 t; cvta.to.shared.u64 t, %1; cvt.u32.u64 %0, t; }"
        : "=r"(a) : "l"(p));
    return a;
}
__device__ __forceinline__ void mma_f16(float c[4], const uint32_t a[4],
                                        const uint32_t b[2]) {
    asm volatile(
        "mma.sync.aligned.m16n8k16.row.col.f32.f16.f16.f32 "
        "{%0,%1,%2,%3}, {%4,%5,%6,%7}, {%8,%9}, {%0,%1,%2,%3};"
        : "+f"(c[0]), "+f"(c[1]), "+f"(c[2]), "+f"(c[3])
        : "r"(a[0]), "r"(a[1]), "r"(a[2]), "r"(a[3]), "r"(b[0]), "r"(b[1]));
}
__device__ __forceinline__ void split_f16(float x, __half& hi, __half& lo) {
    hi = __float2half_rn(x);
    lo = __float2half_rn(x - __half2float(hi));
}
// fma-pipe exp (avoids MUFU bottleneck); |rel err| <= ~2.4e-6 for x <= 0.
__device__ __forceinline__ float fexp(float x) {
    float y = fmaxf(x * 1.44269504f, -120.f);
    int   n = __float2int_rn(y);
    float f = y - (float)n;
    float t = f * 0.69314718f;
    float p = 1.f + t * (1.f + t * (0.5f + t * (0.16666667f +
              t * (0.04166667f + t * 0.00833333f))));
    return p * __int_as_float((n + 127) << 23);
}
#define CP_ASYNC16(dst, src) \
    asm volatile("cp.async.cg.shared.global [%0], [%1], 16;" \
        :: "r"(dst), "l"(src) : "memory")
#define CP_COMMIT() asm volatile("cp.async.commit_group;" ::: "memory")

// ---------------------------------------------------------------------------
// Pre-split kernels.
// split_a: fp32 [M_,E_] -> hi fp16 same layout (lo not needed: 2-term).
// split_b: weights -> k-paired half2 [k2][Ntot], hi and lo.
// ---------------------------------------------------------------------------
template <bool FROM_HID>
__global__ __launch_bounds__(256)
void split_a_r16(const float* __restrict__ src)
{
    const int idx = blockIdx.x * 256 + threadIdx.x;       // float4 index
    const float4 v = ((const float4*)(FROM_HID ? src : (const float*)g_x))[idx];
    __half* dh = FROM_HID ? g_hidh : g_xh;
    __half2 a = __halves2half2(__float2half_rn(v.x), __float2half_rn(v.y));
    __half2 b = __halves2half2(__float2half_rn(v.z), __float2half_rn(v.w));
    ((__half2*)dh)[2*idx]   = a;
    ((__half2*)dh)[2*idx+1] = b;
}

template <bool QKV>
__global__ __launch_bounds__(256)
void split_b_r16(const float* __restrict__ Wq, const float* __restrict__ Wk,
                 const float* __restrict__ Wv, const float* __restrict__ Wo)
{
    const int n  = blockIdx.x * 256 + threadIdx.x;
    const int k2 = blockIdx.y;                             // 0..383
    float v0, v1;
    if (QKV) {
        int proj = n / 768, rem = n - proj * 768;
        int h = rem >> 6, d = rem & 63;
        const float* W = (proj == 0) ? Wq : (proj == 1) ? Wk : Wv;
        size_t base = ((size_t)h * E_ + 2 * k2) * D_ + d;
        v0 = W[base]; v1 = W[base + D_];
    } else {
        v0 = Wo[(size_t)(2 * k2) * E_ + n];
        v1 = Wo[(size_t)(2 * k2 + 1) * E_ + n];
    }
    __half h0,l0,h1,l1;
    split_f16(v0,h0,l0); split_f16(v1,h1,l1);
    const int Ntot = QKV ? 2304 : 768;
    __half2* dh = QKV ? g_wh : g_woh;
    __half2* dl = QKV ? g_wl : g_wol;
    dh[(size_t)k2 * Ntot + n] = __halves2half2(h0, h1);    // (even, odd)
    dl[(size_t)k2 * Ntot + n] = __halves2half2(l0, l1);
}

// ---------------------------------------------------------------------------
// GEMM v3: 2-term hi/lo HMMA (D = Ah*Bh + Ah*Bl), pre-split fp16 inputs,
// cp.async double-buffered staging, 2 CTAs/SM.
// Tile 128x128, 256 thr = 8 warps (2m x 4n), warp tile 64x32.
// Per smem buffer (27648 B): Ahi[128][40]h +0 (10240 B),
// Bhi[16][136]half2 +10240 (8704 B), Blo +18944 (8704 B).
// ---------------------------------------------------------------------------
#define CHUNKS 24     // 768/32
#define BUF_BYTES 27648

template <bool QKV>
__global__ __launch_bounds__(256, 2)
void gemm_v3_r16(const float* __restrict__ bq, const float* __restrict__ bk,
                 const float* __restrict__ bv, const float* __restrict__ bo,
                 float* __restrict__ dout)
{
    extern __shared__ char smc[];
    const uint32_t smb = smem_u32(smc);
    const int Ntot = QKV ? 2304 : 768;

    const int tid = threadIdx.x;
    const int wid = tid >> 5, lane = tid & 31;
    const int g = lane >> 2, c = lane & 3;
    const int wm = wid >> 2, wn = wid & 3;
    const int m0 = blockIdx.x * 128, n0 = blockIdx.y * 128;

    const __half*  Ah = QKV ? g_hidh : g_xh;
    const __half2* Bh = QKV ? g_wh : g_woh;
    const __half2* Bl = QKV ? g_wl : g_wol;

    // staging descriptors (16B segments)
    // A: 128 rows x 32 halfs = 512 segs; f: row=f>>2, seg=f&3
    const int af0 = tid,        af1 = tid + 256;
    const uint32_t adst0 = (af0 >> 2) * 80 + (af0 & 3) * 16;
    const uint32_t adst1 = (af1 >> 2) * 80 + (af1 & 3) * 16;
    const size_t aoff0 = (size_t)(m0 + (af0 >> 2)) * E_ + (af0 & 3) * 8;
    const size_t aoff1 = (size_t)(m0 + (af1 >> 2)) * E_ + (af1 & 3) * 8;
    // B: 16 k2-rows x 128 half2 = 512 segs; f: row=f>>5, off=f&31
    const int bf0 = tid,        bf1 = tid + 256;
    const uint32_t bdst0 = (bf0 >> 5) * 544 + (bf0 & 31) * 16;
    const uint32_t bdst1 = (bf1 >> 5) * 544 + (bf1 & 31) * 16;
    const size_t boff0 = (size_t)(bf0 >> 5) * Ntot + n0 + (bf0 & 31) * 4;
    const size_t boff1 = (size_t)(bf1 >> 5) * Ntot + n0 + (bf1 & 31) * 4;

    auto stage = [&](int t, int p) {
        const uint32_t ab = smb + p * BUF_BYTES;
        const int tk = t * 32;                 // A half offset along k
        const size_t bk16 = (size_t)t * 16 * Ntot;
        CP_ASYNC16(ab + adst0,         Ah + aoff0 + tk);
        CP_ASYNC16(ab + adst1,         Ah + aoff1 + tk);
        CP_ASYNC16(ab + 10240 + bdst0, Bh + boff0 + bk16);
        CP_ASYNC16(ab + 10240 + bdst1, Bh + boff1 + bk16);
        CP_ASYNC16(ab + 18944 + bdst0, Bl + boff0 + bk16);
        CP_ASYNC16(ab + 18944 + bdst1, Bl + boff1 + bk16);
        CP_COMMIT();
    };

    float Cacc[4][4][4];
#pragma unroll
    for (int ms = 0; ms < 4; ms++)
#pragma unroll
        for (int ns = 0; ns < 4; ns++)
#pragma unroll
            for (int r = 0; r < 4; r++) Cacc[ms][ns][r] = 0.f;

    stage(0, 0);

    for (int t = 0; t < CHUNKS; t++) {
        const int p = t & 1;
        if (t + 1 < CHUNKS) {
            stage(t + 1, 1 - p);
            asm volatile("cp.async.wait_group 1;" ::: "memory");
        } else {
            asm volatile("cp.async.wait_group 0;" ::: "memory");
        }
        __syncthreads();

        const uint32_t* Ahi32 = (const uint32_t*)(smc + p * BUF_BYTES);
        const uint32_t* Bhi32 = Ahi32 + 2560;
        const uint32_t* Blo32 = Ahi32 + 4736;

#pragma unroll
        for (int s = 0; s < 2; s++) {
            uint32_t ahi[4][4];
#pragma unroll
            for (int ms = 0; ms < 4; ms++) {
                const int aw = (wm * 64 + ms * 16 + g) * 20 + s * 8 + c;
                ahi[ms][0] = Ahi32[aw];
                ahi[ms][1] = Ahi32[aw + 160];
                ahi[ms][2] = Ahi32[aw + 4];
                ahi[ms][3] = Ahi32[aw + 164];
            }
#pragma unroll
            for (int ns = 0; ns < 4; ns++) {
                const int bw = (s * 8 + c) * 136 + wn * 32 + ns * 8 + g;
                uint32_t bh2[2] = {Bhi32[bw], Bhi32[bw + 544]};
                uint32_t bl2[2] = {Blo32[bw], Blo32[bw + 544]};
#pragma unroll
                for (int ms = 0; ms < 4; ms++) {
                    mma_f16(Cacc[ms][ns], ahi[ms], bh2);
                    mma_f16(Cacc[ms][ns], ahi[ms], bl2);
                }
            }
        }
        __syncthreads();
    }

    // ---- epilogue ----
#pragma unroll
    for (int ms = 0; ms < 4; ms++) {
        const int m = m0 + wm * 64 + ms * 16 + g;
#pragma unroll
        for (int ns = 0; ns < 4; ns++) {
            const int n = n0 + wn * 32 + ns * 8 + 2 * c;
            if (QKV) {
                int proj = n / 768;
                int rem  = n - proj * 768;
                int h = rem >> 6, d = rem & 63;
                const float* bias = ((proj == 0) ? bq : (proj == 1) ? bk : bv) + h * D_;
                float* out = (proj == 0) ? g_q : (proj == 1) ? g_k : g_v;
                float b0 = bias[d], b1 = bias[d + 1];
                int bb = m >> 10, s = m & (S_ - 1);
                float* r0 = out + (((size_t)(bb * H_ + h)) * S_ + s) * D_ + d;
                float* r1 = r0 + 8 * D_;
                *(float2*)r0 = make_float2(Cacc[ms][ns][0] + b0, Cacc[ms][ns][1] + b1);
                *(float2*)r1 = make_float2(Cacc[ms][ns][2] + b0, Cacc[ms][ns][3] + b1);
            } else {
                float b0 = bo[n], b1 = bo[n + 1];
                float* r0 = dout + (size_t)m * E_ + n;
                float* r1 = r0 + (size_t)8 * E_;
                *(float2*)r0 = make_float2(Cacc[ms][ns][0] + b0, Cacc[ms][ns][1] + b1);
                *(float2*)r1 = make_float2(Cacc[ms][ns][2] + b0, Cacc[ms][ns][3] + b1);
            }
        }
    }
}

// ---------------------------------------------------------------------------
// HMMA flash attention, 2-term hi/lo: S = Qh*(Kh+Kl), O = Ph*(Vh+Vl).
// Same layouts/strides as R14/R15 (proven conflict-free).
// ---------------------------------------------------------------------------
__global__ __launch_bounds__(256, 1)
void attn_hmma_r16()
{
    extern __shared__ uint32_t sm2[];
    uint32_t* Khi = sm2;                 // [32][136] half2
    uint32_t* Klo = sm2 + 4352;
    uint32_t* Vhi = sm2 + 8704;          // [64][72] half2
    uint32_t* Vlo = sm2 + 13312;

    const int tid  = threadIdx.x;
    const int wid  = tid >> 5, lane = tid & 31;
    const int g    = lane >> 2, c = lane & 3;
    const int bh   = blockIdx.y;
    const int q0   = blockIdx.x * 128 + wid * 16;

    const float* Q = g_q + (size_t)bh * S_ * D_;
    const float* K = g_k + (size_t)bh * S_ * D_;
    const float* V = g_v + (size_t)bh * S_ * D_;

    // ---- Q A-fragments (hi only), loaded once ----
    uint32_t qhi[4][4];
#pragma unroll
    for (int s = 0; s < 4; s++) {
        float2 x0 = *(const float2*)&Q[(size_t)(q0 + g    ) * D_ + s * 16 + 2 * c];
        float2 x1 = *(const float2*)&Q[(size_t)(q0 + g + 8) * D_ + s * 16 + 2 * c];
        float2 x2 = *(const float2*)&Q[(size_t)(q0 + g    ) * D_ + s * 16 + 8 + 2 * c];
        float2 x3 = *(const float2*)&Q[(size_t)(q0 + g + 8) * D_ + s * 16 + 8 + 2 * c];
        float2 xs[4] = {x0, x1, x2, x3};
#pragma unroll
        for (int r = 0; r < 4; r++) {
            __half2 hh = __floats2half2_rn(xs[r].x, xs[r].y);
            qhi[s][r] = *(uint32_t*)&hh;
        }
    }

    float m0r = -1e30f, m1r = -1e30f, l0r = 0.f, l1r = 0.f;
    float Oa[8][4];
#pragma unroll
    for (int ns = 0; ns < 8; ns++)
#pragma unroll
        for (int r = 0; r < 4; r++) Oa[ns][r] = 0.f;

    for (int t0 = 0; t0 < S_; t0 += 128) {
        __syncthreads();
        // ---- stage K tile (hi+lo, k-paired along d) ----
#pragma unroll
        for (int i = 0; i < 8; i++) {
            int f = i * 256 + tid;
            int kr = f & 127, d4 = f >> 7;
            float4 kv = *(const float4*)&K[(size_t)(t0 + kr) * D_ + d4 * 4];
            __half h0, l0, h1, l1, h2, l2, h3, l3;
            split_f16(kv.x, h0, l0); split_f16(kv.y, h1, l1);
            split_f16(kv.z, h2, l2); split_f16(kv.w, h3, l3);
            __half2 a = __halves2half2(h0, h1), b = __halves2half2(h2, h3);
            __half2 e = __halves2half2(l0, l1), d = __halves2half2(l2, l3);
            Khi[(2 * d4 + 0) * 136 + kr] = *(uint32_t*)&a;
            Khi[(2 * d4 + 1) * 136 + kr] = *(uint32_t*)&b;
            Klo[(2 * d4 + 0) * 136 + kr] = *(uint32_t*)&e;
            Klo[(2 * d4 + 1) * 136 + kr] = *(uint32_t*)&d;
        }
        // ---- stage V tile (hi+lo, k-paired along kv rows) ----
        {
            __half* VhiH = (__half*)Vhi;
            __half* VloH = (__half*)Vlo;
#pragma unroll
            for (int i = 0; i < 8; i++) {
                int kr = i * 16 + (tid >> 4);
                int n4 = tid & 15;
                float4 vv = *(const float4*)&V[(size_t)(t0 + kr) * D_ + n4 * 4];
                float xs[4] = {vv.x, vv.y, vv.z, vv.w};
                int base = ((kr >> 1) * 72 + n4 * 4) * 2 + (kr & 1);
#pragma unroll
                for (int j = 0; j < 4; j++) {
                    __half h, l;
                    split_f16(xs[j], h, l);
                    VhiH[base + j * 2] = h;
                    VloH[base + j * 2] = l;
                }
            }
        }
        __syncthreads();

        // ---- S = Qh * (Kh + Kl) ----
        float Sa[16][4];
#pragma unroll
        for (int ns = 0; ns < 16; ns++)
#pragma unroll
            for (int r = 0; r < 4; r++) Sa[ns][r] = 0.f;
#pragma unroll
        for (int s = 0; s < 4; s++) {
#pragma unroll
            for (int ns = 0; ns < 16; ns++) {
                uint32_t bhi[2], blo[2];
                const int bw = (s * 8 + c) * 136 + ns * 8 + g;
                bhi[0] = Khi[bw]; bhi[1] = Khi[bw + 544];
                blo[0] = Klo[bw]; blo[1] = Klo[bw + 544];
                mma_f16(Sa[ns], qhi[s], bhi);
                mma_f16(Sa[ns], qhi[s], blo);
            }
        }

        // ---- online softmax ----
        float mx0 = -1e30f, mx1 = -1e30f;
#pragma unroll
        for (int ns = 0; ns < 16; ns++) {
            Sa[ns][0] *= 0.125f; Sa[ns][1] *= 0.125f;
            Sa[ns][2] *= 0.125f; Sa[ns][3] *= 0.125f;
            mx0 = fmaxf(mx0, fmaxf(Sa[ns][0], Sa[ns][1]));
            mx1 = fmaxf(mx1, fmaxf(Sa[ns][2], Sa[ns][3]));
        }
        mx0 = fmaxf(mx0, __shfl_xor_sync(0xffffffffu, mx0, 1));
        mx0 = fmaxf(mx0, __shfl_xor_sync(0xffffffffu, mx0, 2));
        mx1 = fmaxf(mx1, __shfl_xor_sync(0xffffffffu, mx1, 1));
        mx1 = fmaxf(mx1, __shfl_xor_sync(0xffffffffu, mx1, 2));
        float mn0 = fmaxf(m0r, mx0), mn1 = fmaxf(m1r, mx1);
        float corr0 = fexp(m0r - mn0), corr1 = fexp(m1r - mn1);
        float sum0 = 0.f, sum1 = 0.f;
#pragma unroll
        for (int ns = 0; ns < 16; ns++) {
            Sa[ns][0] = fexp(Sa[ns][0] - mn0); sum0 += Sa[ns][0];
            Sa[ns][1] = fexp(Sa[ns][1] - mn0); sum0 += Sa[ns][1];
            Sa[ns][2] = fexp(Sa[ns][2] - mn1); sum1 += Sa[ns][2];
            Sa[ns][3] = fexp(Sa[ns][3] - mn1); sum1 += Sa[ns][3];
        }
        sum0 += __shfl_xor_sync(0xffffffffu, sum0, 1);
        sum0 += __shfl_xor_sync(0xffffffffu, sum0, 2);
        sum1 += __shfl_xor_sync(0xffffffffu, sum1, 1);
        sum1 += __shfl_xor_sync(0xffffffffu, sum1, 2);
        l0r = l0r * corr0 + sum0; m0r = mn0;
        l1r = l1r * corr1 + sum1; m1r = mn1;
#pragma unroll
        for (int ns = 0; ns < 8; ns++) {
            Oa[ns][0] *= corr0; Oa[ns][1] *= corr0;
            Oa[ns][2] *= corr1; Oa[ns][3] *= corr1;
        }

        // ---- P -> A fragments (hi only, single convert) ----
        uint32_t phi[8][4];
#pragma unroll
        for (int s = 0; s < 8; s++) {
            float v[4][2] = {{Sa[2*s][0],   Sa[2*s][1]},
                             {Sa[2*s][2],   Sa[2*s][3]},
                             {Sa[2*s+1][0], Sa[2*s+1][1]},
                             {Sa[2*s+1][2], Sa[2*s+1][3]}};
#pragma unroll
            for (int r = 0; r < 4; r++) {
                __half2 hh = __floats2half2_rn(v[r][0], v[r][1]);
                phi[s][r] = *(uint32_t*)&hh;
            }
        }

        // ---- O += Ph * (Vh + Vl) ----
#pragma unroll
        for (int s = 0; s < 8; s++) {
#pragma unroll
            for (int ns = 0; ns < 8; ns++) {
                uint32_t bhi[2], blo[2];
                const int bw = (s * 8 + c) * 72 + ns * 8 + g;
                bhi[0] = Vhi[bw]; bhi[1] = Vhi[bw + 288];
                blo[0] = Vlo[bw]; blo[1] = Vlo[bw + 288];
                mma_f16(Oa[ns], phi[s], bhi);
                mma_f16(Oa[ns], phi[s], blo);
            }
        }
    }

    // ---- epilogue: write head-concatenated g_x ----
    const float inv0 = 1.f / l0r, inv1 = 1.f / l1r;
    const int b = bh / H_, h = bh - b * H_;
    float* r0 = g_x + ((size_t)b * S_ + q0 + g    ) * E_ + h * 64 + 2 * c;
    float* r1 = g_x + ((size_t)b * S_ + q0 + g + 8) * E_ + h * 64 + 2 * c;
#pragma unroll
    for (int ns = 0; ns < 8; ns++) {
        *(float2*)(r0 + ns * 8) = make_float2(Oa[ns][0] * inv0, Oa[ns][1] * inv0);
        *(float2*)(r1 + ns * 8) = make_float2(Oa[ns][2] * inv1, Oa[ns][3] * inv1);
    }
}

// ---------------------------------------------------------------------------

extern "C" void kernel_launch(void* const* d_in, const int* in_sizes, int n_in,
                              void* d_out, int out_size)
{
    const float* hid = (const float*)d_in[0];
    const float* Wq  = (const float*)d_in[1];
    const float* Wk  = (const float*)d_in[2];
    const float* Wv  = (const float*)d_in[3];
    const float* bq  = (const float*)d_in[4];
    const float* bk  = (const float*)d_in[5];
    const float* bv  = (const float*)d_in[6];
    const float* Wo  = (const float*)d_in[7];
    const float* bo  = (const float*)d_in[8];
    float* out = (float*)d_out;

    const int attn_smem = 71680;
    const int gemm_smem = 2 * BUF_BYTES;   // 55296
    cudaFuncSetAttribute(attn_hmma_r16,
                         cudaFuncAttributeMaxDynamicSharedMemorySize, attn_smem);
    cudaFuncSetAttribute(gemm_v3_r16<true>,
                         cudaFuncAttributeMaxDynamicSharedMemorySize, gemm_smem);
    cudaFuncSetAttribute(gemm_v3_r16<false>,
                         cudaFuncAttributeMaxDynamicSharedMemorySize, gemm_smem);

    // 0) pre-split inputs
    split_a_r16<true><<<M_ * E_ / 4 / 256, 256>>>(hid);
    split_b_r16<true><<<dim3(2304 / 256, E_ / 2), 256>>>(Wq, Wk, Wv, nullptr);
    split_b_r16<false><<<dim3(768 / 256, E_ / 2), 256>>>(nullptr, nullptr, nullptr, Wo);

    // 1) fused QKV projection
    gemm_v3_r16<true><<<dim3(M_ / 128, 2304 / 128), 256, gemm_smem>>>(
        bq, bk, bv, nullptr, nullptr);

    // 2) attention
    attn_hmma_r16<<<dim3(S_ / 128, B_ * H_), 256, attn_smem>>>();

    // 3) split attention output, then output projection
    split_a_r16<false><<<M_ * E_ / 4 / 256, 256>>>(nullptr);
    gemm_v3_r16<false><<<dim3(M_ / 128, 768 / 128), 256, gemm_smem>>>(
        nullptr, nullptr, nullptr, bo, out);
}

// round 17
// speedup vs baseline: 4.5380x; 1.2262x over previous
#include <cuda_runtime.h>
#include <cuda_fp16.h>
#include <cstdint>

#define B_ 8
#define S_ 1024
#define E_ 768
#define H_ 12
#define D_ 64
#define M_ (B_*S_)   // 8192
#define BH_ (B_*H_)  // 96

// ---------------------------------------------------------------------------
// Scratch (allocations forbidden; device globals). NEVER pass these as kernel
// args from host (GB300 HMM/ATS silently reads the host shadow — R6-R11 bug).
// ---------------------------------------------------------------------------
// qkv outputs in attention-ready fp16 layouts:
__device__ __half  g_qh [BH_*S_*D_];          // Q hi rows       [bh][s][d]
__device__ __half2 g_khp[BH_*(D_/2)*S_];      // K hi, d-paired  [bh][d2][s]
__device__ __half2 g_klp[BH_*(D_/2)*S_];      // K lo
__device__ __half  g_vth[BH_*D_*S_];          // V hi transposed [bh][d][s]
__device__ __half  g_vtl[BH_*D_*S_];          // V lo
__device__ __half  g_xh [M_*E_];              // attn out hi     [b][s][e]
// pre-split GEMM operands:
__device__ __half  g_hidh[M_*E_];                          // A for qkv GEMM
__device__ __half2 g_wh[(E_/2)*2304], g_wl[(E_/2)*2304];   // B qkv, k-paired
__device__ __half2 g_woh[(E_/2)*E_],  g_wol[(E_/2)*E_];    // B proj, k-paired

// ---------------------------------------------------------------------------
// Helpers
// ---------------------------------------------------------------------------
__device__ __forceinline__ uint32_t smem_u32(const void* p) {
    uint32_t a;
    asm("{ .reg .u64 t; cvta.to.shared.u64 t, %1; cvt.u32.u64 %0, t; }"
        : "=r"(a) : "l"(p));
    return a;
}
__device__ __forceinline__ void mma_f16(float c[4], const uint32_t a[4],
                                        const uint32_t b[2]) {
    asm volatile(
        "mma.sync.aligned.m16n8k16.row.col.f32.f16.f16.f32 "
        "{%0,%1,%2,%3}, {%4,%5,%6,%7}, {%8,%9}, {%0,%1,%2,%3};"
        : "+f"(c[0]), "+f"(c[1]), "+f"(c[2]), "+f"(c[3])
        : "r"(a[0]), "r"(a[1]), "r"(a[2]), "r"(a[3]), "r"(b[0]), "r"(b[1]));
}
__device__ __forceinline__ void split_f16(float x, __half& hi, __half& lo) {
    hi = __float2half_rn(x);
    lo = __float2half_rn(x - __half2float(hi));
}
// fma-pipe exp (avoids MUFU bottleneck); |rel err| <= ~2.4e-6 for x <= 0.
__device__ __forceinline__ float fexp(float x) {
    float y = fmaxf(x * 1.44269504f, -120.f);
    int   n = __float2int_rn(y);
    float f = y - (float)n;
    float t = f * 0.69314718f;
    float p = 1.f + t * (1.f + t * (0.5f + t * (0.16666667f +
              t * (0.04166667f + t * 0.00833333f))));
    return p * __int_as_float((n + 127) << 23);
}
#define CP_ASYNC16(dst, src) \
    asm volatile("cp.async.cg.shared.global [%0], [%1], 16;" \
        :: "r"(dst), "l"(src) : "memory")
#define CP_COMMIT() asm volatile("cp.async.commit_group;" ::: "memory")

// ---------------------------------------------------------------------------
// Pre-split kernels (inputs only).
// ---------------------------------------------------------------------------
__global__ __launch_bounds__(256)
void split_hid_r17(const float* __restrict__ src)
{
    const int idx = blockIdx.x * 256 + threadIdx.x;       // float4 index
    const float4 v = ((const float4*)src)[idx];
    __half2 a = __halves2half2(__float2half_rn(v.x), __float2half_rn(v.y));
    __half2 b = __halves2half2(__float2half_rn(v.z), __float2half_rn(v.w));
    ((__half2*)g_hidh)[2*idx]   = a;
    ((__half2*)g_hidh)[2*idx+1] = b;
}

template <bool QKV>
__global__ __launch_bounds__(256)
void split_b_r17(const float* __restrict__ Wq, const float* __restrict__ Wk,
                 const float* __restrict__ Wv, const float* __restrict__ Wo)
{
    const int n  = blockIdx.x * 256 + threadIdx.x;
    const int k2 = blockIdx.y;                             // 0..383
    float v0, v1;
    if (QKV) {
        int proj = n / 768, rem = n - proj * 768;
        int h = rem >> 6, d = rem & 63;
        const float* W = (proj == 0) ? Wq : (proj == 1) ? Wk : Wv;
        size_t base = ((size_t)h * E_ + 2 * k2) * D_ + d;
        v0 = W[base]; v1 = W[base + D_];
    } else {
        v0 = Wo[(size_t)(2 * k2) * E_ + n];
        v1 = Wo[(size_t)(2 * k2 + 1) * E_ + n];
    }
    __half h0,l0,h1,l1;
    split_f16(v0,h0,l0); split_f16(v1,h1,l1);
    const int Ntot = QKV ? 2304 : 768;
    __half2* dh = QKV ? g_wh : g_woh;
    __half2* dl = QKV ? g_wl : g_wol;
    dh[(size_t)k2 * Ntot + n] = __halves2half2(h0, h1);    // (even, odd)
    dl[(size_t)k2 * Ntot + n] = __halves2half2(l0, l1);
}

// ---------------------------------------------------------------------------
// GEMM: 2-term hi/lo HMMA (D = Ah*Bh + Ah*Bl), cp.async double-buffered.
// Identical mainloop to R16; only the QKV epilogue changed (fp16 layouts).
// ---------------------------------------------------------------------------
#define CHUNKS 24     // 768/32
#define BUF_BYTES 27648

template <bool QKV>
__global__ __launch_bounds__(256, 2)
void gemm_v4_r17(const float* __restrict__ bq, const float* __restrict__ bk,
                 const float* __restrict__ bv, const float* __restrict__ bo,
                 float* __restrict__ dout)
{
    extern __shared__ char smc[];
    const uint32_t smb = smem_u32(smc);
    const int Ntot = QKV ? 2304 : 768;

    const int tid = threadIdx.x;
    const int wid = tid >> 5, lane = tid & 31;
    const int g = lane >> 2, c = lane & 3;
    const int wm = wid >> 2, wn = wid & 3;
    const int m0 = blockIdx.x * 128, n0 = blockIdx.y * 128;

    const __half*  Ah = QKV ? g_hidh : g_xh;
    const __half2* Bh = QKV ? g_wh : g_woh;
    const __half2* Bl = QKV ? g_wl : g_wol;

    const int af0 = tid,        af1 = tid + 256;
    const uint32_t adst0 = (af0 >> 2) * 80 + (af0 & 3) * 16;
    const uint32_t adst1 = (af1 >> 2) * 80 + (af1 & 3) * 16;
    const size_t aoff0 = (size_t)(m0 + (af0 >> 2)) * E_ + (af0 & 3) * 8;
    const size_t aoff1 = (size_t)(m0 + (af1 >> 2)) * E_ + (af1 & 3) * 8;
    const int bf0 = tid,        bf1 = tid + 256;
    const uint32_t bdst0 = (bf0 >> 5) * 544 + (bf0 & 31) * 16;
    const uint32_t bdst1 = (bf1 >> 5) * 544 + (bf1 & 31) * 16;
    const size_t boff0 = (size_t)(bf0 >> 5) * Ntot + n0 + (bf0 & 31) * 4;
    const size_t boff1 = (size_t)(bf1 >> 5) * Ntot + n0 + (bf1 & 31) * 4;

    auto stage = [&](int t, int p) {
        const uint32_t ab = smb + p * BUF_BYTES;
        const int tk = t * 32;
        const size_t bk16 = (size_t)t * 16 * Ntot;
        CP_ASYNC16(ab + adst0,         Ah + aoff0 + tk);
        CP_ASYNC16(ab + adst1,         Ah + aoff1 + tk);
        CP_ASYNC16(ab + 10240 + bdst0, Bh + boff0 + bk16);
        CP_ASYNC16(ab + 10240 + bdst1, Bh + boff1 + bk16);
        CP_ASYNC16(ab + 18944 + bdst0, Bl + boff0 + bk16);
        CP_ASYNC16(ab + 18944 + bdst1, Bl + boff1 + bk16);
        CP_COMMIT();
    };

    float Cacc[4][4][4];
#pragma unroll
    for (int ms = 0; ms < 4; ms++)
#pragma unroll
        for (int ns = 0; ns < 4; ns++)
#pragma unroll
            for (int r = 0; r < 4; r++) Cacc[ms][ns][r] = 0.f;

    stage(0, 0);

    for (int t = 0; t < CHUNKS; t++) {
        const int p = t & 1;
        if (t + 1 < CHUNKS) {
            stage(t + 1, 1 - p);
            asm volatile("cp.async.wait_group 1;" ::: "memory");
        } else {
            asm volatile("cp.async.wait_group 0;" ::: "memory");
        }
        __syncthreads();

        const uint32_t* Ahi32 = (const uint32_t*)(smc + p * BUF_BYTES);
        const uint32_t* Bhi32 = Ahi32 + 2560;
        const uint32_t* Blo32 = Ahi32 + 4736;

#pragma unroll
        for (int s = 0; s < 2; s++) {
            uint32_t ahi[4][4];
#pragma unroll
            for (int ms = 0; ms < 4; ms++) {
                const int aw = (wm * 64 + ms * 16 + g) * 20 + s * 8 + c;
                ahi[ms][0] = Ahi32[aw];
                ahi[ms][1] = Ahi32[aw + 160];
                ahi[ms][2] = Ahi32[aw + 4];
                ahi[ms][3] = Ahi32[aw + 164];
            }
#pragma unroll
            for (int ns = 0; ns < 4; ns++) {
                const int bw = (s * 8 + c) * 136 + wn * 32 + ns * 8 + g;
                uint32_t bh2[2] = {Bhi32[bw], Bhi32[bw + 544]};
                uint32_t bl2[2] = {Blo32[bw], Blo32[bw + 544]};
#pragma unroll
                for (int ms = 0; ms < 4; ms++) {
                    mma_f16(Cacc[ms][ns], ahi[ms], bh2);
                    mma_f16(Cacc[ms][ns], ahi[ms], bl2);
                }
            }
        }
        __syncthreads();
    }

    // ---- epilogue ----
#pragma unroll
    for (int ms = 0; ms < 4; ms++) {
        const int m = m0 + wm * 64 + ms * 16 + g;
#pragma unroll
        for (int ns = 0; ns < 4; ns++) {
            const int n = n0 + wn * 32 + ns * 8 + 2 * c;
            if (QKV) {
                int proj = n / 768;
                int rem  = n - proj * 768;
                int h = rem >> 6, d = rem & 63;        // d even
                const float* bias = ((proj == 0) ? bq : (proj == 1) ? bk : bv) + h * D_;
                float b0 = bias[d], b1 = bias[d + 1];
                int bb = m >> 10, s = m & (S_ - 1);
                const int bh = bb * H_ + h;
                float v0 = Cacc[ms][ns][0] + b0, v1 = Cacc[ms][ns][1] + b1;
                float v2 = Cacc[ms][ns][2] + b0, v3 = Cacc[ms][ns][3] + b1;  // row m+8
                if (proj == 0) {
                    __half2* q0p = (__half2*)&g_qh[((size_t)bh * S_ + s) * D_ + d];
                    __half2* q1p = (__half2*)&g_qh[((size_t)bh * S_ + s + 8) * D_ + d];
                    *q0p = __floats2half2_rn(v0, v1);
                    *q1p = __floats2half2_rn(v2, v3);
                } else if (proj == 1) {
                    const size_t kbase = ((size_t)bh * (D_/2) + (d >> 1)) * S_;
                    __half h0,l0,h1,l1;
                    split_f16(v0,h0,l0); split_f16(v1,h1,l1);
                    g_khp[kbase + s] = __halves2half2(h0, h1);
                    g_klp[kbase + s] = __halves2half2(l0, l1);
                    split_f16(v2,h0,l0); split_f16(v3,h1,l1);
                    g_khp[kbase + s + 8] = __halves2half2(h0, h1);
                    g_klp[kbase + s + 8] = __halves2half2(l0, l1);
                } else {
                    const size_t v0b = ((size_t)bh * D_ + d) * S_;
                    const size_t v1b = ((size_t)bh * D_ + d + 1) * S_;
                    __half h0,l0,h1,l1;
                    split_f16(v0,h0,l0); split_f16(v1,h1,l1);
                    g_vth[v0b + s] = h0; g_vtl[v0b + s] = l0;
                    g_vth[v1b + s] = h1; g_vtl[v1b + s] = l1;
                    split_f16(v2,h0,l0); split_f16(v3,h1,l1);
                    g_vth[v0b + s + 8] = h0; g_vtl[v0b + s + 8] = l0;
                    g_vth[v1b + s + 8] = h1; g_vtl[v1b + s + 8] = l1;
                }
            } else {
                float b0 = bo[n], b1 = bo[n + 1];
                float* r0 = dout + (size_t)m * E_ + n;
                float* r1 = r0 + (size_t)8 * E_;
                *(float2*)r0 = make_float2(Cacc[ms][ns][0] + b0, Cacc[ms][ns][1] + b1);
                *(float2*)r1 = make_float2(Cacc[ms][ns][2] + b0, Cacc[ms][ns][3] + b1);
            }
        }
    }
}

// ---------------------------------------------------------------------------
// HMMA flash attention v2: pre-split fp16 K/V staged by cp.async,
// double-buffered; Q fragments loaded directly from fp16 global.
// Per buffer (69632 B): Khi[32][136]h2 +0, Klo +17408, VT hi [64][68]h2
// +34816, VT lo +52224. Two buffers = 139264 B dynamic.
// V^T fragment: b0 = VT[(ns*8+g)*68 + s*8+c], b1 = +4 (banks 4g+c: CF).
// ---------------------------------------------------------------------------
#define ABUF 69632

__global__ __launch_bounds__(256, 1)
void attn_hmma_r17()
{
    extern __shared__ char asmc[];
    const uint32_t smb = smem_u32(asmc);

    const int tid  = threadIdx.x;
    const int wid  = tid >> 5, lane = tid & 31;
    const int g    = lane >> 2, c = lane & 3;
    const int bh   = blockIdx.y;
    const int q0   = blockIdx.x * 128 + wid * 16;

    const __half* Qh = g_qh + (size_t)bh * S_ * D_;
    // staging sources
    const __half2* Khg = g_khp + (size_t)bh * (D_/2) * S_;
    const __half2* Klg = g_klp + (size_t)bh * (D_/2) * S_;
    const __half*  Vhg = g_vth + (size_t)bh * D_ * S_;
    const __half*  Vlg = g_vtl + (size_t)bh * D_ * S_;

    // per-thread staging descriptors (4 segs per array per tile)
    // K: seg f: d2 = f>>5 (0..31), j = f&31 ; 16B = 4 half2 along s
    // V: seg f: d  = f>>4 (0..63), j = f&15 ; 16B = 8 halfs along s
    auto stage = [&](int t0, int p) {
        const uint32_t ab = smb + p * ABUF;
#pragma unroll
        for (int i = 0; i < 4; i++) {
            const int f = i * 256 + tid;
            const int d2 = f >> 5, j = f & 31;
            const size_t src = (size_t)d2 * S_ + t0 + j * 4;
            CP_ASYNC16(ab + d2 * 544 + j * 16,         Khg + src);
            CP_ASYNC16(ab + 17408 + d2 * 544 + j * 16, Klg + src);
        }
#pragma unroll
        for (int i = 0; i < 4; i++) {
            const int f = i * 256 + tid;
            const int d = f >> 4, j = f & 15;
            const size_t src = (size_t)d * S_ + t0 + j * 8;
            CP_ASYNC16(ab + 34816 + d * 272 + j * 16, Vhg + src);
            CP_ASYNC16(ab + 52224 + d * 272 + j * 16, Vlg + src);
        }
        CP_COMMIT();
    };

    // ---- Q A-fragments (hi only) straight from fp16 global ----
    uint32_t qhi[4][4];
    {
        const uint32_t* Q32 = (const uint32_t*)Qh;
        const int r0w = (q0 + g) * 32, r1w = (q0 + g + 8) * 32;
#pragma unroll
        for (int s = 0; s < 4; s++) {
            qhi[s][0] = Q32[r0w + s * 8 + c];
            qhi[s][1] = Q32[r1w + s * 8 + c];
            qhi[s][2] = Q32[r0w + s * 8 + c + 4];
            qhi[s][3] = Q32[r1w + s * 8 + c + 4];
        }
    }

    float m0r = -1e30f, m1r = -1e30f, l0r = 0.f, l1r = 0.f;
    float Oa[8][4];
#pragma unroll
    for (int ns = 0; ns < 8; ns++)
#pragma unroll
        for (int r = 0; r < 4; r++) Oa[ns][r] = 0.f;

    stage(0, 0);

    for (int t0 = 0; t0 < S_; t0 += 128) {
        const int p = (t0 >> 7) & 1;
        if (t0 + 128 < S_) {
            stage(t0 + 128, 1 - p);
            asm volatile("cp.async.wait_group 1;" ::: "memory");
        } else {
            asm volatile("cp.async.wait_group 0;" ::: "memory");
        }
        __syncthreads();

        const uint32_t* Khi = (const uint32_t*)(asmc + p * ABUF);
        const uint32_t* Klo = Khi + 4352;
        const uint32_t* VTh = Khi + 8704;
        const uint32_t* VTl = Khi + 13056;

        // ---- S = Qh * (Kh + Kl) ----
        float Sa[16][4];
#pragma unroll
        for (int ns = 0; ns < 16; ns++)
#pragma unroll
            for (int r = 0; r < 4; r++) Sa[ns][r] = 0.f;
#pragma unroll
        for (int s = 0; s < 4; s++) {
#pragma unroll
            for (int ns = 0; ns < 16; ns++) {
                const int bw = (s * 8 + c) * 136 + ns * 8 + g;
                uint32_t bhi[2] = {Khi[bw], Khi[bw + 544]};
                uint32_t blo[2] = {Klo[bw], Klo[bw + 544]};
                mma_f16(Sa[ns], qhi[s], bhi);
                mma_f16(Sa[ns], qhi[s], blo);
            }
        }

        // ---- online softmax ----
        float mx0 = -1e30f, mx1 = -1e30f;
#pragma unroll
        for (int ns = 0; ns < 16; ns++) {
            Sa[ns][0] *= 0.125f; Sa[ns][1] *= 0.125f;
            Sa[ns][2] *= 0.125f; Sa[ns][3] *= 0.125f;
            mx0 = fmaxf(mx0, fmaxf(Sa[ns][0], Sa[ns][1]));
            mx1 = fmaxf(mx1, fmaxf(Sa[ns][2], Sa[ns][3]));
        }
        mx0 = fmaxf(mx0, __shfl_xor_sync(0xffffffffu, mx0, 1));
        mx0 = fmaxf(mx0, __shfl_xor_sync(0xffffffffu, mx0, 2));
        mx1 = fmaxf(mx1, __shfl_xor_sync(0xffffffffu, mx1, 1));
        mx1 = fmaxf(mx1, __shfl_xor_sync(0xffffffffu, mx1, 2));
        float mn0 = fmaxf(m0r, mx0), mn1 = fmaxf(m1r, mx1);
        float corr0 = fexp(m0r - mn0), corr1 = fexp(m1r - mn1);
        float sum0 = 0.f, sum1 = 0.f;
#pragma unroll
        for (int ns = 0; ns < 16; ns++) {
            Sa[ns][0] = fexp(Sa[ns][0] - mn0); sum0 += Sa[ns][0];
            Sa[ns][1] = fexp(Sa[ns][1] - mn0); sum0 += Sa[ns][1];
            Sa[ns][2] = fexp(Sa[ns][2] - mn1); sum1 += Sa[ns][2];
            Sa[ns][3] = fexp(Sa[ns][3] - mn1); sum1 += Sa[ns][3];
        }
        sum0 += __shfl_xor_sync(0xffffffffu, sum0, 1);
        sum0 += __shfl_xor_sync(0xffffffffu, sum0, 2);
        sum1 += __shfl_xor_sync(0xffffffffu, sum1, 1);
        sum1 += __shfl_xor_sync(0xffffffffu, sum1, 2);
        l0r = l0r * corr0 + sum0; m0r = mn0;
        l1r = l1r * corr1 + sum1; m1r = mn1;
#pragma unroll
        for (int ns = 0; ns < 8; ns++) {
            Oa[ns][0] *= corr0; Oa[ns][1] *= corr0;
            Oa[ns][2] *= corr1; Oa[ns][3] *= corr1;
        }

        // ---- P -> A fragments (hi only) ----
        uint32_t phi[8][4];
#pragma unroll
        for (int s = 0; s < 8; s++) {
            float v[4][2] = {{Sa[2*s][0],   Sa[2*s][1]},
                             {Sa[2*s][2],   Sa[2*s][3]},
                             {Sa[2*s+1][0], Sa[2*s+1][1]},
                             {Sa[2*s+1][2], Sa[2*s+1][3]}};
#pragma unroll
            for (int r = 0; r < 4; r++) {
                __half2 hh = __floats2half2_rn(v[r][0], v[r][1]);
                phi[s][r] = *(uint32_t*)&hh;
            }
        }

        // ---- O += Ph * (Vh + Vl), V^T layout ----
#pragma unroll
        for (int s = 0; s < 8; s++) {
#pragma unroll
            for (int ns = 0; ns < 8; ns++) {
                const int bw = (ns * 8 + g) * 68 + s * 8 + c;
                uint32_t bhi[2] = {VTh[bw], VTh[bw + 4]};
                uint32_t blo[2] = {VTl[bw], VTl[bw + 4]};
                mma_f16(Oa[ns], phi[s], bhi);
                mma_f16(Oa[ns], phi[s], blo);
            }
        }
        __syncthreads();
    }

    // ---- epilogue: write g_xh fp16 (proj GEMM A operand) ----
    const float inv0 = 1.f / l0r, inv1 = 1.f / l1r;
    const int b = bh / H_, h = bh - b * H_;
    __half* r0 = g_xh + ((size_t)b * S_ + q0 + g    ) * E_ + h * 64 + 2 * c;
    __half* r1 = g_xh + ((size_t)b * S_ + q0 + g + 8) * E_ + h * 64 + 2 * c;
#pragma unroll
    for (int ns = 0; ns < 8; ns++) {
        *(__half2*)(r0 + ns * 8) = __floats2half2_rn(Oa[ns][0] * inv0, Oa[ns][1] * inv0);
        *(__half2*)(r1 + ns * 8) = __floats2half2_rn(Oa[ns][2] * inv1, Oa[ns][3] * inv1);
    }
}

// ---------------------------------------------------------------------------

extern "C" void kernel_launch(void* const* d_in, const int* in_sizes, int n_in,
                              void* d_out, int out_size)
{
    const float* hid = (const float*)d_in[0];
    const float* Wq  = (const float*)d_in[1];
    const float* Wk  = (const float*)d_in[2];
    const float* Wv  = (const float*)d_in[3];
    const float* bq  = (const float*)d_in[4];
    const float* bk  = (const float*)d_in[5];
    const float* bv  = (const float*)d_in[6];
    const float* Wo  = (const float*)d_in[7];
    const float* bo  = (const float*)d_in[8];
    float* out = (float*)d_out;

    const int attn_smem = 2 * ABUF;        // 139264
    const int gemm_smem = 2 * BUF_BYTES;   // 55296
    cudaFuncSetAttribute(attn_hmma_r17,
                         cudaFuncAttributeMaxDynamicSharedMemorySize, attn_smem);
    cudaFuncSetAttribute(gemm_v4_r17<true>,
                         cudaFuncAttributeMaxDynamicSharedMemorySize, gemm_smem);
    cudaFuncSetAttribute(gemm_v4_r17<false>,
                         cudaFuncAttributeMaxDynamicSharedMemorySize, gemm_smem);

    // 0) pre-split inputs
    split_hid_r17<<<M_ * E_ / 4 / 256, 256>>>(hid);
    split_b_r17<true><<<dim3(2304 / 256, E_ / 2), 256>>>(Wq, Wk, Wv, nullptr);
    split_b_r17<false><<<dim3(768 / 256, E_ / 2), 256>>>(nullptr, nullptr, nullptr, Wo);

    // 1) fused QKV projection (epilogue emits attention-ready fp16 layouts)
    gemm_v4_r17<true><<<dim3(M_ / 128, 2304 / 128), 256, gemm_smem>>>(
        bq, bk, bv, nullptr, nullptr);

    // 2) attention (cp.async double-buffered KV)
    attn_hmma_r17<<<dim3(S_ / 128, BH_), 256, attn_smem>>>();

    // 3) output projection (A = g_xh written by attention)
    gemm_v4_r17<false><<<dim3(M_ / 128, 768 / 128), 256, gemm_smem>>>(
        nullptr, nullptr, nullptr, bo, out);
}